// round 4
// baseline (speedup 1.0000x reference)
#include <cuda_runtime.h>
#include <cstdint>

#define TOKS 8192
#define HDIM 1024
#define FDIM 4096
#define NEXP 8

// ---------------- scratch (__device__ globals; no allocation) ----------------
__device__ int   g_cnt[NEXP];
__device__ int   g_off[NEXP];
__device__ int   g_tok[NEXP * TOKS];
__device__ int   g_slot[NEXP * TOKS];
__device__ float g_wt[NEXP * TOKS];
__device__ float g_h[(size_t)2 * TOKS * FDIM];   // 16384 x 4096 fp32 (256 MB)
__device__ float g_y[(size_t)2 * TOKS * HDIM];   // 2 x 8192 x 1024 fp32 (64 MB)

// ---------------- helpers ----------------
static __device__ __forceinline__ uint32_t smem_u32(const void* p) {
    uint32_t a;
    asm("{ .reg .u64 t; cvta.to.shared.u64 t, %1; cvt.u32.u64 %0, t; }" : "=r"(a) : "l"(p));
    return a;
}
static __device__ __forceinline__ uint32_t f2tf(float f) {
    uint32_t u;
    asm("cvt.rna.tf32.f32 %0, %1;" : "=r"(u) : "f"(f));
    return u;
}
static __device__ __forceinline__ void mma8(float* c, const uint32_t* a, const uint32_t* b) {
    asm volatile(
        "mma.sync.aligned.m16n8k8.row.col.f32.tf32.tf32.f32 "
        "{%0,%1,%2,%3}, {%4,%5,%6,%7}, {%8,%9}, {%0,%1,%2,%3};"
        : "+f"(c[0]), "+f"(c[1]), "+f"(c[2]), "+f"(c[3])
        : "r"(a[0]), "r"(a[1]), "r"(a[2]), "r"(a[3]), "r"(b[0]), "r"(b[1]));
}
#define CP16(dst, src, sz) \
    asm volatile("cp.async.cg.shared.global [%0], [%1], 16, %2;\n" ::"r"(dst), "l"(src), "r"(sz))
#define CP_COMMIT() asm volatile("cp.async.commit_group;\n" ::: "memory")
#define CP_WAIT1()  asm volatile("cp.async.wait_group 1;\n" ::: "memory")
#define CP_WAIT0()  asm volatile("cp.async.wait_group 0;\n" ::: "memory")

static __device__ __forceinline__ float silu(float v) { return v / (1.f + __expf(-v)); }

// ---------------- router ----------------
__global__ void moe_router(const float* __restrict__ x, const float* __restrict__ wg,
                           float* __restrict__ logits_out) {
    int t = blockIdx.x * 8 + (threadIdx.x >> 5);
    int lane = threadIdx.x & 31;
    const float* xr = x + (size_t)t * HDIM;
    float acc[8] = {0.f, 0.f, 0.f, 0.f, 0.f, 0.f, 0.f, 0.f};
    for (int j = lane; j < HDIM; j += 32) {
        float xv = xr[j];
        const float4* w4 = reinterpret_cast<const float4*>(wg + (size_t)j * NEXP);
        float4 a = w4[0], b = w4[1];
        acc[0] += xv * a.x; acc[1] += xv * a.y; acc[2] += xv * a.z; acc[3] += xv * a.w;
        acc[4] += xv * b.x; acc[5] += xv * b.y; acc[6] += xv * b.z; acc[7] += xv * b.w;
    }
#pragma unroll
    for (int o = 16; o > 0; o >>= 1)
#pragma unroll
        for (int k = 0; k < 8; k++) acc[k] += __shfl_xor_sync(0xffffffffu, acc[k], o);

    if (lane == 0) {
#pragma unroll
        for (int k = 0; k < 8; k++) logits_out[(size_t)t * NEXP + k] = acc[k];
        int i0 = 0; float v0 = acc[0];
#pragma unroll
        for (int k = 1; k < 8; k++) if (acc[k] > v0) { v0 = acc[k]; i0 = k; }
        int i1 = -1; float v1 = -3.4e38f;
#pragma unroll
        for (int k = 0; k < 8; k++) if (k != i0 && acc[k] > v1) { v1 = acc[k]; i1 = k; }
        // renormalized top-2: p0/(p0+p1) == 1/(1+exp(l1-l0)), l0 >= l1 (stable)
        float w0 = 1.f / (1.f + __expf(v1 - v0));
        float w1 = 1.f - w0;
        int p0 = atomicAdd(&g_cnt[i0], 1);
        g_tok[i0 * TOKS + p0] = t; g_slot[i0 * TOKS + p0] = 0; g_wt[i0 * TOKS + p0] = w0;
        int p1 = atomicAdd(&g_cnt[i1], 1);
        g_tok[i1 * TOKS + p1] = t; g_slot[i1 * TOKS + p1] = 1; g_wt[i1 * TOKS + p1] = w1;
    }
}

__global__ void moe_zero() { if (threadIdx.x < NEXP) g_cnt[threadIdx.x] = 0; }

__global__ void moe_offsets() {
    int s = 0;
    for (int e = 0; e < NEXP; e++) { g_off[e] = s; s += g_cnt[e]; }
}

// ---------------- grouped GEMM: C[128x128] per CTA, mma.sync tf32 ----------------
// MODE 0: gate  : C = gather(x) @ Wg   -> g_h = silu(C)
// MODE 1: up    : C = gather(x) @ Wu   -> g_h = g_h * C
// MODE 2: down  : C = g_h @ Wd         -> g_y[slot][tok] = w * C   (A source = g_h, taken
//                                         from the DEVICE symbol inside the kernel)
// A pitch 36 floats, B pitch 136 floats (both conflict-free for frag loads).
// Smem floats: A[2][128*36]=9216, B[2][32*136]=8704 -> 17920 fl = 71680 B.

template <int MODE, int KD, int NTOT>
__global__ void __launch_bounds__(256, 2)
moe_gemm(const float* __restrict__ Ag, const float* __restrict__ Bg) {
    int e = blockIdx.z;
    int cnt = g_cnt[e];
    int base = blockIdx.y * 128;
    if (base >= cnt) return;
    int n0 = blockIdx.x * 128;
    int off = g_off[e];
    const float* Be = Bg + (size_t)e * KD * NTOT;
    // A source: device-global scratch for MODE 2 (never pass __device__ symbols from host!)
    const float* Asrc = (MODE == 2) ? (const float*)g_h : Ag;

    extern __shared__ float smem[];
    float* sA[2] = {smem, smem + 4608};
    float* sB[2] = {smem + 9216, smem + 9216 + 4352};
    uint32_t su = smem_u32(smem);
    uint32_t sAu[2] = {su, su + 4608 * 4};
    uint32_t sBu[2] = {su + 9216 * 4, su + (9216 + 4352) * 4};

    int tid = threadIdx.x;
    int lane = tid & 31;
    int gid = lane >> 2, tig = lane & 3;
    int wm = (tid >> 5) >> 2;   // 0..1
    int wn = (tid >> 5) & 3;    // 0..3

    // --- per-thread load descriptors ---
    const float* asrc[4]; uint32_t asz[4], adst[4];
#pragma unroll
    for (int j = 0; j < 4; j++) {
        int idx = tid + j * 256;
        int row = idx >> 3, c4 = idx & 7;
        int r = base + row;
        bool v = r < cnt;
        size_t arow;
        if (MODE == 2) arow = v ? (size_t)(off + r) : 0;
        else           arow = v ? (size_t)g_tok[e * TOKS + r] : 0;
        asrc[j] = Asrc + arow * KD + c4 * 4;
        asz[j] = v ? 16u : 0u;
        adst[j] = (uint32_t)(row * 144 + c4 * 16);
    }
    const float* bsrc[4]; uint32_t bdst[4];
#pragma unroll
    for (int j = 0; j < 4; j++) {
        int idx = tid + j * 256;
        int k = idx >> 5, c = idx & 31;
        bsrc[j] = Be + (size_t)k * NTOT + n0 + c * 4;
        bdst[j] = (uint32_t)(k * 544 + c * 16);
    }

    float acc[4][4][4];
#pragma unroll
    for (int m = 0; m < 4; m++)
#pragma unroll
        for (int n = 0; n < 4; n++)
#pragma unroll
            for (int q = 0; q < 4; q++) acc[m][n][q] = 0.f;

    const int KI = KD / 32;

    // prefetch stage 0
#pragma unroll
    for (int j = 0; j < 4; j++) CP16(sAu[0] + adst[j], asrc[j], asz[j]);
#pragma unroll
    for (int j = 0; j < 4; j++) CP16(sBu[0] + bdst[j], bsrc[j], 16u);
    CP_COMMIT();

    for (int i = 0; i < KI; i++) {
        if (i + 1 < KI) {
            int s = (i + 1) & 1;
            int k0 = (i + 1) * 32;
#pragma unroll
            for (int j = 0; j < 4; j++) CP16(sAu[s] + adst[j], asrc[j] + k0, asz[j]);
#pragma unroll
            for (int j = 0; j < 4; j++) CP16(sBu[s] + bdst[j], bsrc[j] + (size_t)k0 * NTOT, 16u);
            CP_COMMIT();
            CP_WAIT1();
        } else {
            CP_WAIT0();
        }
        __syncthreads();
        const float* As = sA[i & 1];
        const float* Bs = sB[i & 1];
#pragma unroll
        for (int k8 = 0; k8 < 4; k8++) {
            uint32_t af[4][4];
#pragma unroll
            for (int m = 0; m < 4; m++) {
                int R = wm * 64 + m * 16 + gid;
                int C = k8 * 8 + tig;
                af[m][0] = f2tf(As[R * 36 + C]);
                af[m][1] = f2tf(As[(R + 8) * 36 + C]);
                af[m][2] = f2tf(As[R * 36 + C + 4]);
                af[m][3] = f2tf(As[(R + 8) * 36 + C + 4]);
            }
            uint32_t bf[4][2];
#pragma unroll
            for (int n = 0; n < 4; n++) {
                int Kr = k8 * 8 + tig;
                int Nc = wn * 32 + n * 8 + gid;
                bf[n][0] = f2tf(Bs[Kr * 136 + Nc]);
                bf[n][1] = f2tf(Bs[(Kr + 4) * 136 + Nc]);
            }
#pragma unroll
            for (int m = 0; m < 4; m++)
#pragma unroll
                for (int n = 0; n < 4; n++) mma8(acc[m][n], af[m], bf[n]);
        }
        __syncthreads();
    }

    // --- epilogue ---
#pragma unroll
    for (int m = 0; m < 4; m++) {
#pragma unroll
        for (int half = 0; half < 2; half++) {
            int R = wm * 64 + m * 16 + gid + half * 8;
            int r = base + R;
            if (r >= cnt) continue;
            if (MODE == 0) {
                size_t rb = (size_t)(off + r) * FDIM + n0;
#pragma unroll
                for (int n = 0; n < 4; n++) {
                    int col = wn * 32 + n * 8 + 2 * tig;
                    float v0 = acc[m][n][half * 2 + 0], v1 = acc[m][n][half * 2 + 1];
                    *reinterpret_cast<float2*>(g_h + rb + col) =
                        make_float2(silu(v0), silu(v1));
                }
            } else if (MODE == 1) {
                size_t rb = (size_t)(off + r) * FDIM + n0;
#pragma unroll
                for (int n = 0; n < 4; n++) {
                    int col = wn * 32 + n * 8 + 2 * tig;
                    float v0 = acc[m][n][half * 2 + 0], v1 = acc[m][n][half * 2 + 1];
                    float2 p = *reinterpret_cast<const float2*>(g_h + rb + col);
                    *reinterpret_cast<float2*>(g_h + rb + col) =
                        make_float2(p.x * v0, p.y * v1);
                }
            } else {
                int t = g_tok[e * TOKS + r];
                int sl = g_slot[e * TOKS + r];
                float w = g_wt[e * TOKS + r];
                size_t yb = ((size_t)sl * TOKS + t) * HDIM + n0;
#pragma unroll
                for (int n = 0; n < 4; n++) {
                    int col = wn * 32 + n * 8 + 2 * tig;
                    float v0 = acc[m][n][half * 2 + 0], v1 = acc[m][n][half * 2 + 1];
                    *reinterpret_cast<float2*>(g_y + yb + col) =
                        make_float2(w * v0, w * v1);
                }
            }
        }
    }
}

// ---------------- combine: out = y[slot0] + y[slot1] ----------------
__global__ void moe_combine(float* __restrict__ out) {
    size_t i = (size_t)blockIdx.x * 256 + threadIdx.x;
    const float4* y0 = reinterpret_cast<const float4*>(g_y);
    const float4* y1 = y0 + (size_t)TOKS * HDIM / 4;
    float4 a = y0[i], b = y1[i];
    reinterpret_cast<float4*>(out)[i] = make_float4(a.x + b.x, a.y + b.y, a.z + b.z, a.w + b.w);
}

// ---------------- launch ----------------
extern "C" void kernel_launch(void* const* d_in, const int* in_sizes, int n_in,
                              void* d_out, int out_size) {
    const float* x   = (const float*)d_in[0];
    const float* wg  = (const float*)d_in[1];
    const float* wgp = (const float*)d_in[2];
    const float* wup = (const float*)d_in[3];
    const float* wdp = (const float*)d_in[4];
    float* out = (float*)d_out;

    const int SMEM = 71680;
    cudaFuncSetAttribute(moe_gemm<0, HDIM, FDIM>, cudaFuncAttributeMaxDynamicSharedMemorySize, SMEM);
    cudaFuncSetAttribute(moe_gemm<1, HDIM, FDIM>, cudaFuncAttributeMaxDynamicSharedMemorySize, SMEM);
    cudaFuncSetAttribute(moe_gemm<2, FDIM, HDIM>, cudaFuncAttributeMaxDynamicSharedMemorySize, SMEM);

    moe_zero<<<1, 32>>>();
    moe_router<<<TOKS / 8, 256>>>(x, wg, out + (size_t)TOKS * HDIM);
    moe_offsets<<<1, 1>>>();
    moe_gemm<0, HDIM, FDIM><<<dim3(FDIM / 128, TOKS / 128, NEXP), 256, SMEM>>>(x, wgp);
    moe_gemm<1, HDIM, FDIM><<<dim3(FDIM / 128, TOKS / 128, NEXP), 256, SMEM>>>(x, wup);
    moe_gemm<2, FDIM, HDIM><<<dim3(HDIM / 128, TOKS / 128, NEXP), 256, SMEM>>>(nullptr, wdp);
    moe_combine<<<(TOKS * HDIM / 4) / 256, 256>>>(out);
}

// round 5
// speedup vs baseline: 1.2821x; 1.2821x over previous
#include <cuda_runtime.h>
#include <cstdint>

#define TOKS 8192
#define HDIM 1024
#define FDIM 4096
#define NEXP 8

// ---------------- scratch (__device__ globals; no allocation) ----------------
__device__ int   g_cnt[NEXP];
__device__ int   g_off[NEXP];
__device__ int   g_tok[NEXP * TOKS];
__device__ int   g_slot[NEXP * TOKS];
__device__ float g_wt[NEXP * TOKS];
__device__ float g_x[(size_t)TOKS * HDIM];       // tf32-rounded copy of x (32 MB)
__device__ float g_h[(size_t)2 * TOKS * FDIM];   // 16384 x 4096 fp32 (256 MB), tf32-rounded
__device__ float g_y[(size_t)2 * TOKS * HDIM];   // 2 x 8192 x 1024 fp32 (64 MB)

// ---------------- helpers ----------------
static __device__ __forceinline__ uint32_t smem_u32(const void* p) {
    uint32_t a;
    asm("{ .reg .u64 t; cvta.to.shared.u64 t, %1; cvt.u32.u64 %0, t; }" : "=r"(a) : "l"(p));
    return a;
}
static __device__ __forceinline__ uint32_t f2tf(float f) {
    uint32_t u;
    asm("cvt.rna.tf32.f32 %0, %1;" : "=r"(u) : "f"(f));
    return u;
}
static __device__ __forceinline__ void mma8(float* c, const uint32_t* a, const uint32_t* b) {
    asm volatile(
        "mma.sync.aligned.m16n8k8.row.col.f32.tf32.tf32.f32 "
        "{%0,%1,%2,%3}, {%4,%5,%6,%7}, {%8,%9}, {%0,%1,%2,%3};"
        : "+f"(c[0]), "+f"(c[1]), "+f"(c[2]), "+f"(c[3])
        : "r"(a[0]), "r"(a[1]), "r"(a[2]), "r"(a[3]), "r"(b[0]), "r"(b[1]));
}
#define CP16(dst, src, sz) \
    asm volatile("cp.async.cg.shared.global [%0], [%1], 16, %2;\n" ::"r"(dst), "l"(src), "r"(sz))
#define CP_COMMIT() asm volatile("cp.async.commit_group;\n" ::: "memory")
#define CP_WAIT1()  asm volatile("cp.async.wait_group 1;\n" ::: "memory")
#define CP_WAIT0()  asm volatile("cp.async.wait_group 0;\n" ::: "memory")

static __device__ __forceinline__ float silu(float v) { return v / (1.f + __expf(-v)); }

// ---------------- pre-round x to tf32 grid (zero low mantissa bits) ----------------
__global__ void moe_round_x(const float* __restrict__ x) {
    size_t i = (size_t)blockIdx.x * 256 + threadIdx.x;
    float4 v = reinterpret_cast<const float4*>(x)[i];
    v.x = __uint_as_float(f2tf(v.x));
    v.y = __uint_as_float(f2tf(v.y));
    v.z = __uint_as_float(f2tf(v.z));
    v.w = __uint_as_float(f2tf(v.w));
    reinterpret_cast<float4*>(g_x)[i] = v;
}

// ---------------- router ----------------
__global__ void moe_router(const float* __restrict__ x, const float* __restrict__ wg,
                           float* __restrict__ logits_out) {
    int t = blockIdx.x * 8 + (threadIdx.x >> 5);
    int lane = threadIdx.x & 31;
    const float* xr = x + (size_t)t * HDIM;
    float acc[8] = {0.f, 0.f, 0.f, 0.f, 0.f, 0.f, 0.f, 0.f};
    for (int j = lane; j < HDIM; j += 32) {
        float xv = xr[j];
        const float4* w4 = reinterpret_cast<const float4*>(wg + (size_t)j * NEXP);
        float4 a = w4[0], b = w4[1];
        acc[0] += xv * a.x; acc[1] += xv * a.y; acc[2] += xv * a.z; acc[3] += xv * a.w;
        acc[4] += xv * b.x; acc[5] += xv * b.y; acc[6] += xv * b.z; acc[7] += xv * b.w;
    }
#pragma unroll
    for (int o = 16; o > 0; o >>= 1)
#pragma unroll
        for (int k = 0; k < 8; k++) acc[k] += __shfl_xor_sync(0xffffffffu, acc[k], o);

    if (lane == 0) {
#pragma unroll
        for (int k = 0; k < 8; k++) logits_out[(size_t)t * NEXP + k] = acc[k];
        int i0 = 0; float v0 = acc[0];
#pragma unroll
        for (int k = 1; k < 8; k++) if (acc[k] > v0) { v0 = acc[k]; i0 = k; }
        int i1 = -1; float v1 = -3.4e38f;
#pragma unroll
        for (int k = 0; k < 8; k++) if (k != i0 && acc[k] > v1) { v1 = acc[k]; i1 = k; }
        // renormalized top-2: p0/(p0+p1) == 1/(1+exp(l1-l0)), l0 >= l1 (stable)
        float w0 = 1.f / (1.f + __expf(v1 - v0));
        float w1 = 1.f - w0;
        int p0 = atomicAdd(&g_cnt[i0], 1);
        g_tok[i0 * TOKS + p0] = t; g_slot[i0 * TOKS + p0] = 0; g_wt[i0 * TOKS + p0] = w0;
        int p1 = atomicAdd(&g_cnt[i1], 1);
        g_tok[i1 * TOKS + p1] = t; g_slot[i1 * TOKS + p1] = 1; g_wt[i1 * TOKS + p1] = w1;
    }
}

__global__ void moe_zero() { if (threadIdx.x < NEXP) g_cnt[threadIdx.x] = 0; }

__global__ void moe_offsets() {
    int s = 0;
    for (int e = 0; e < NEXP; e++) { g_off[e] = s; s += g_cnt[e]; }
}

// ---------------- fused gate+up GEMM ----------------
// C_g, C_u [128 x 64] per CTA over K=1024; epilogue: g_h = tf32(silu(C_g) * C_u).
// A from g_x (pre-rounded: raw-bit MMA feed, no cvt). B gets cvt on fragment load.
// smem per stage (floats): A 128x36=4608, Bg 32x72=2304, Bu 2304 -> 9216 fl = 36864 B.
// 3 stages = 110592 B; 2 CTAs/SM = 221184 <= 228 KB.
__global__ void __launch_bounds__(256, 2)
moe_gateup(const float* __restrict__ Wg, const float* __restrict__ Wu) {
    int e = blockIdx.z;
    int cnt = g_cnt[e];
    int base = blockIdx.y * 128;
    if (base >= cnt) return;
    int n0 = blockIdx.x * 64;
    int off = g_off[e];
    const float* wge = Wg + (size_t)e * HDIM * FDIM;
    const float* wue = Wu + (size_t)e * HDIM * FDIM;

    extern __shared__ float smem[];
    uint32_t su = smem_u32(smem);

    int tid = threadIdx.x, lane = tid & 31;
    int gid = lane >> 2, tig = lane & 3;
    int wid = tid >> 5, wm = wid >> 2, wn = wid & 3;

    // A: 128 rows x 8 x 16B chunks -> 4 per thread
    const float* asrc[4]; uint32_t asz[4], adst[4];
#pragma unroll
    for (int j = 0; j < 4; j++) {
        int idx = tid + j * 256;
        int row = idx >> 3, c4 = idx & 7;
        int r = base + row;
        bool v = r < cnt;
        int tok = v ? g_tok[e * TOKS + r] : 0;
        asrc[j] = g_x + (size_t)tok * HDIM + c4 * 4;
        asz[j] = v ? 16u : 0u;
        adst[j] = (uint32_t)(row * 144 + c4 * 16);
    }
    // B (each side): 32 k-rows x 16 x 16B chunks -> 2 per thread per side
    const float* gsrc[2]; const float* usrc[2]; uint32_t bdst[2];
#pragma unroll
    for (int j = 0; j < 2; j++) {
        int idx = tid + j * 256;
        int k = idx >> 4, c = idx & 15;
        gsrc[j] = wge + (size_t)k * FDIM + n0 + c * 4;
        usrc[j] = wue + (size_t)k * FDIM + n0 + c * 4;
        bdst[j] = (uint32_t)(k * 288 + c * 16);
    }

    float accG[4][2][4], accU[4][2][4];
#pragma unroll
    for (int m = 0; m < 4; m++)
#pragma unroll
        for (int n = 0; n < 2; n++)
#pragma unroll
            for (int q = 0; q < 4; q++) { accG[m][n][q] = 0.f; accU[m][n][q] = 0.f; }

    const int KI = HDIM / 32;  // 32

#define GU_ISSUE(s, k0)                                                              \
    do {                                                                             \
        uint32_t ab = su + (uint32_t)(s) * 36864u;                                   \
        uint32_t gb = ab + 18432u, ub = ab + 27648u;                                 \
        _Pragma("unroll") for (int j = 0; j < 4; j++)                                \
            CP16(ab + adst[j], asrc[j] + (k0), asz[j]);                              \
        _Pragma("unroll") for (int j = 0; j < 2; j++)                                \
            CP16(gb + bdst[j], gsrc[j] + (size_t)(k0) * FDIM, 16u);                  \
        _Pragma("unroll") for (int j = 0; j < 2; j++)                                \
            CP16(ub + bdst[j], usrc[j] + (size_t)(k0) * FDIM, 16u);                  \
        CP_COMMIT();                                                                 \
    } while (0)

    GU_ISSUE(0, 0);
    GU_ISSUE(1, 32);

    int sC = 0, sN = 2;
    for (int i = 0; i < KI; i++) {
        if (i + 1 < KI) CP_WAIT1(); else CP_WAIT0();
        __syncthreads();
        if (i + 2 < KI) {
            GU_ISSUE(sN, (i + 2) * 32);
            sN = (sN == 2) ? 0 : sN + 1;
        }
        const uint32_t* As = reinterpret_cast<const uint32_t*>(smem + sC * 9216);
        const float* Bgs = smem + sC * 9216 + 4608;
        const float* Bus = Bgs + 2304;
        sC = (sC == 2) ? 0 : sC + 1;
#pragma unroll
        for (int k8 = 0; k8 < 4; k8++) {
            uint32_t af[4][4];
#pragma unroll
            for (int m = 0; m < 4; m++) {
                int R = wm * 64 + m * 16 + gid;
                int C = k8 * 8 + tig;
                af[m][0] = As[R * 36 + C];
                af[m][1] = As[(R + 8) * 36 + C];
                af[m][2] = As[R * 36 + C + 4];
                af[m][3] = As[(R + 8) * 36 + C + 4];
            }
            uint32_t bg[2][2], bu[2][2];
#pragma unroll
            for (int n = 0; n < 2; n++) {
                int Kr = k8 * 8 + tig;
                int Nc = wn * 16 + n * 8 + gid;
                bg[n][0] = f2tf(Bgs[Kr * 72 + Nc]);
                bg[n][1] = f2tf(Bgs[(Kr + 4) * 72 + Nc]);
                bu[n][0] = f2tf(Bus[Kr * 72 + Nc]);
                bu[n][1] = f2tf(Bus[(Kr + 4) * 72 + Nc]);
            }
#pragma unroll
            for (int m = 0; m < 4; m++)
#pragma unroll
                for (int n = 0; n < 2; n++) {
                    mma8(accG[m][n], af[m], bg[n]);
                    mma8(accU[m][n], af[m], bu[n]);
                }
        }
    }
#undef GU_ISSUE

    // epilogue: g_h = tf32-rounded silu(g)*u (raw-bit A feed for the down GEMM)
#pragma unroll
    for (int m = 0; m < 4; m++) {
#pragma unroll
        for (int half = 0; half < 2; half++) {
            int R = wm * 64 + m * 16 + gid + half * 8;
            int r = base + R;
            if (r >= cnt) continue;
            size_t rb = (size_t)(off + r) * FDIM + n0;
#pragma unroll
            for (int n = 0; n < 2; n++) {
                int col = wn * 16 + n * 8 + 2 * tig;
                float h0 = silu(accG[m][n][half * 2 + 0]) * accU[m][n][half * 2 + 0];
                float h1 = silu(accG[m][n][half * 2 + 1]) * accU[m][n][half * 2 + 1];
                *reinterpret_cast<float2*>(g_h + rb + col) =
                    make_float2(__uint_as_float(f2tf(h0)), __uint_as_float(f2tf(h1)));
            }
        }
    }
}

// ---------------- down GEMM: y[slot][tok] = w * (g_h @ Wd) ----------------
// C [128 x 128] per CTA over K=4096. A = g_h (pre-rounded, raw-bit feed).
// smem per stage (floats): A 128x36=4608, B 32x136=4352 -> 8960 fl = 35840 B.
// 3 stages = 107520 B; 2 CTAs/SM = 215040 <= 228 KB.
__global__ void __launch_bounds__(256, 2)
moe_down(const float* __restrict__ Wd) {
    int e = blockIdx.z;
    int cnt = g_cnt[e];
    int base = blockIdx.y * 128;
    if (base >= cnt) return;
    int n0 = blockIdx.x * 128;
    int off = g_off[e];
    const float* wde = Wd + (size_t)e * FDIM * HDIM;

    extern __shared__ float smem[];
    uint32_t su = smem_u32(smem);

    int tid = threadIdx.x, lane = tid & 31;
    int gid = lane >> 2, tig = lane & 3;
    int wid = tid >> 5, wm = wid >> 2, wn = wid & 3;

    const float* asrc[4]; uint32_t asz[4], adst[4];
#pragma unroll
    for (int j = 0; j < 4; j++) {
        int idx = tid + j * 256;
        int row = idx >> 3, c4 = idx & 7;
        int r = base + row;
        bool v = r < cnt;
        size_t arow = v ? (size_t)(off + r) : 0;
        asrc[j] = g_h + arow * FDIM + c4 * 4;
        asz[j] = v ? 16u : 0u;
        adst[j] = (uint32_t)(row * 144 + c4 * 16);
    }
    const float* bsrc[4]; uint32_t bdst[4];
#pragma unroll
    for (int j = 0; j < 4; j++) {
        int idx = tid + j * 256;
        int k = idx >> 5, c = idx & 31;
        bsrc[j] = wde + (size_t)k * HDIM + n0 + c * 4;
        bdst[j] = (uint32_t)(k * 544 + c * 16);
    }

    float acc[4][4][4];
#pragma unroll
    for (int m = 0; m < 4; m++)
#pragma unroll
        for (int n = 0; n < 4; n++)
#pragma unroll
            for (int q = 0; q < 4; q++) acc[m][n][q] = 0.f;

    const int KI = FDIM / 32;  // 128

#define DN_ISSUE(s, k0)                                                              \
    do {                                                                             \
        uint32_t ab = su + (uint32_t)(s) * 35840u;                                   \
        uint32_t bb = ab + 18432u;                                                   \
        _Pragma("unroll") for (int j = 0; j < 4; j++)                                \
            CP16(ab + adst[j], asrc[j] + (k0), asz[j]);                              \
        _Pragma("unroll") for (int j = 0; j < 4; j++)                                \
            CP16(bb + bdst[j], bsrc[j] + (size_t)(k0) * HDIM, 16u);                  \
        CP_COMMIT();                                                                 \
    } while (0)

    DN_ISSUE(0, 0);
    DN_ISSUE(1, 32);

    int sC = 0, sN = 2;
    for (int i = 0; i < KI; i++) {
        if (i + 1 < KI) CP_WAIT1(); else CP_WAIT0();
        __syncthreads();
        if (i + 2 < KI) {
            DN_ISSUE(sN, (i + 2) * 32);
            sN = (sN == 2) ? 0 : sN + 1;
        }
        const uint32_t* As = reinterpret_cast<const uint32_t*>(smem + sC * 8960);
        const float* Bs = smem + sC * 8960 + 4608;
        sC = (sC == 2) ? 0 : sC + 1;
#pragma unroll
        for (int k8 = 0; k8 < 4; k8++) {
            uint32_t af[4][4];
#pragma unroll
            for (int m = 0; m < 4; m++) {
                int R = wm * 64 + m * 16 + gid;
                int C = k8 * 8 + tig;
                af[m][0] = As[R * 36 + C];
                af[m][1] = As[(R + 8) * 36 + C];
                af[m][2] = As[R * 36 + C + 4];
                af[m][3] = As[(R + 8) * 36 + C + 4];
            }
            uint32_t bf[4][2];
#pragma unroll
            for (int n = 0; n < 4; n++) {
                int Kr = k8 * 8 + tig;
                int Nc = wn * 32 + n * 8 + gid;
                bf[n][0] = f2tf(Bs[Kr * 136 + Nc]);
                bf[n][1] = f2tf(Bs[(Kr + 4) * 136 + Nc]);
            }
#pragma unroll
            for (int m = 0; m < 4; m++)
#pragma unroll
                for (int n = 0; n < 4; n++) mma8(acc[m][n], af[m], bf[n]);
        }
    }
#undef DN_ISSUE

    // epilogue: weighted scatter to slot buffers
#pragma unroll
    for (int m = 0; m < 4; m++) {
#pragma unroll
        for (int half = 0; half < 2; half++) {
            int R = wm * 64 + m * 16 + gid + half * 8;
            int r = base + R;
            if (r >= cnt) continue;
            int t = g_tok[e * TOKS + r];
            int sl = g_slot[e * TOKS + r];
            float w = g_wt[e * TOKS + r];
            size_t yb = ((size_t)sl * TOKS + t) * HDIM + n0;
#pragma unroll
            for (int n = 0; n < 4; n++) {
                int col = wn * 32 + n * 8 + 2 * tig;
                float v0 = acc[m][n][half * 2 + 0], v1 = acc[m][n][half * 2 + 1];
                *reinterpret_cast<float2*>(g_y + yb + col) = make_float2(w * v0, w * v1);
            }
        }
    }
}

// ---------------- combine: out = y[slot0] + y[slot1] ----------------
__global__ void moe_combine(float* __restrict__ out) {
    size_t i = (size_t)blockIdx.x * 256 + threadIdx.x;
    const float4* y0 = reinterpret_cast<const float4*>(g_y);
    const float4* y1 = y0 + (size_t)TOKS * HDIM / 4;
    float4 a = y0[i], b = y1[i];
    reinterpret_cast<float4*>(out)[i] = make_float4(a.x + b.x, a.y + b.y, a.z + b.z, a.w + b.w);
}

// ---------------- launch ----------------
extern "C" void kernel_launch(void* const* d_in, const int* in_sizes, int n_in,
                              void* d_out, int out_size) {
    const float* x   = (const float*)d_in[0];
    const float* wg  = (const float*)d_in[1];
    const float* wgp = (const float*)d_in[2];
    const float* wup = (const float*)d_in[3];
    const float* wdp = (const float*)d_in[4];
    float* out = (float*)d_out;

    cudaFuncSetAttribute(moe_gateup, cudaFuncAttributeMaxDynamicSharedMemorySize, 110592);
    cudaFuncSetAttribute(moe_down,   cudaFuncAttributeMaxDynamicSharedMemorySize, 107520);

    moe_zero<<<1, 32>>>();
    moe_round_x<<<(TOKS * HDIM / 4) / 256, 256>>>(x);
    moe_router<<<TOKS / 8, 256>>>(x, wg, out + (size_t)TOKS * HDIM);
    moe_offsets<<<1, 1>>>();
    moe_gateup<<<dim3(FDIM / 64, TOKS / 128, NEXP), 256, 110592>>>(wgp, wup);
    moe_down<<<dim3(HDIM / 128, TOKS / 128, NEXP), 256, 107520>>>(wdp);
    moe_combine<<<(TOKS * HDIM / 4) / 256, 256>>>(out);
}

// round 7
// speedup vs baseline: 2.0173x; 1.5734x over previous
#include <cuda_runtime.h>
#include <cuda_fp16.h>
#include <cstdint>

#define TOKS 8192
#define HDIM 1024
#define FDIM 4096
#define NEXP 8

// ---------------- scratch (__device__ globals; no allocation) ----------------
__device__ int    g_cnt[NEXP];
__device__ int    g_off[NEXP];
__device__ int    g_tok[NEXP * TOKS];
__device__ int    g_slot[NEXP * TOKS];
__device__ float  g_wt[NEXP * TOKS];
__device__ __half g_x16[(size_t)TOKS * HDIM];            // fp16 x (16 MB)
__device__ __half g_wg16[(size_t)NEXP * FDIM * HDIM];    // gate W, [e][n][k] (64 MB)
__device__ __half g_wu16[(size_t)NEXP * FDIM * HDIM];    // up   W, [e][n][k] (64 MB)
__device__ __half g_wd16[(size_t)NEXP * HDIM * FDIM];    // down W, [e][n][k] (64 MB)
__device__ __half g_h16[(size_t)2 * TOKS * FDIM];        // hidden (128 MB)
__device__ float  g_y[(size_t)2 * TOKS * HDIM];          // slot outputs (64 MB)

// ---------------- helpers ----------------
static __device__ __forceinline__ uint32_t smem_u32(const void* p) {
    uint32_t a;
    asm("{ .reg .u64 t; cvta.to.shared.u64 t, %1; cvt.u32.u64 %0, t; }" : "=r"(a) : "l"(p));
    return a;
}
static __device__ __forceinline__ void mma16(float* c, const uint32_t* a, const uint32_t* b) {
    asm volatile(
        "mma.sync.aligned.m16n8k16.row.col.f32.f16.f16.f32 "
        "{%0,%1,%2,%3}, {%4,%5,%6,%7}, {%8,%9}, {%0,%1,%2,%3};"
        : "+f"(c[0]), "+f"(c[1]), "+f"(c[2]), "+f"(c[3])
        : "r"(a[0]), "r"(a[1]), "r"(a[2]), "r"(a[3]), "r"(b[0]), "r"(b[1]));
}
#define CP16(dst, src, sz) \
    asm volatile("cp.async.cg.shared.global [%0], [%1], 16, %2;\n" ::"r"(dst), "l"(src), "r"(sz))
#define CP_COMMIT() asm volatile("cp.async.commit_group;\n" ::: "memory")
#define CP_WAITG2() asm volatile("cp.async.wait_group 2;\n" ::: "memory")
#define CP_WAITG1() asm volatile("cp.async.wait_group 1;\n" ::: "memory")
#define CP_WAIT0()  asm volatile("cp.async.wait_group 0;\n" ::: "memory")

static __device__ __forceinline__ float silu(float v) { return v / (1.f + __expf(-v)); }

// ---------------- convert x -> fp16 ----------------
__global__ void conv_x(const float* __restrict__ x) {
    size_t i = ((size_t)blockIdx.x * 256 + threadIdx.x) * 8;
    float4 a = *reinterpret_cast<const float4*>(x + i);
    float4 b = *reinterpret_cast<const float4*>(x + i + 4);
    __half2 h[4];
    h[0] = __floats2half2_rn(a.x, a.y);
    h[1] = __floats2half2_rn(a.z, a.w);
    h[2] = __floats2half2_rn(b.x, b.y);
    h[3] = __floats2half2_rn(b.z, b.w);
    *reinterpret_cast<uint4*>(g_x16 + i) = *reinterpret_cast<uint4*>(h);
}

// ---------------- convert+transpose W: [e][k][n] fp32 -> [e][n][k] fp16 ----------------
__global__ void conv_w(const float* __restrict__ src, __half* __restrict__ dst,
                       int Kd, int Nd) {
    __shared__ float t[64][65];
    int e = blockIdx.z;
    int k0 = blockIdx.y * 64, n0 = blockIdx.x * 64;
    const float* S = src + ((size_t)e * Kd + k0) * Nd + n0;
    int tid = threadIdx.x;
    int kr = tid >> 4, nc = (tid & 15) * 4;
#pragma unroll
    for (int j = 0; j < 4; j++) {
        float4 v = *reinterpret_cast<const float4*>(S + (size_t)(kr + j * 16) * Nd + nc);
        t[kr + j * 16][nc + 0] = v.x;
        t[kr + j * 16][nc + 1] = v.y;
        t[kr + j * 16][nc + 2] = v.z;
        t[kr + j * 16][nc + 3] = v.w;
    }
    __syncthreads();
    int nr = tid >> 2, kc = (tid & 3) * 16;
    __half hb[16];
#pragma unroll
    for (int q = 0; q < 16; q++) hb[q] = __float2half_rn(t[kc + q][nr]);
    __half* D = dst + ((size_t)e * Nd + n0 + nr) * Kd + k0 + kc;
    *reinterpret_cast<uint4*>(D)     = *reinterpret_cast<uint4*>(hb);
    *reinterpret_cast<uint4*>(D + 8) = *reinterpret_cast<uint4*>(hb + 8);
}

// ---------------- router ----------------
__global__ void moe_router(const float* __restrict__ x, const float* __restrict__ wg,
                           float* __restrict__ logits_out) {
    int t = blockIdx.x * 8 + (threadIdx.x >> 5);
    int lane = threadIdx.x & 31;
    const float* xr = x + (size_t)t * HDIM;
    float acc[8] = {0.f, 0.f, 0.f, 0.f, 0.f, 0.f, 0.f, 0.f};
    for (int j = lane; j < HDIM; j += 32) {
        float xv = xr[j];
        const float4* w4 = reinterpret_cast<const float4*>(wg + (size_t)j * NEXP);
        float4 a = w4[0], b = w4[1];
        acc[0] += xv * a.x; acc[1] += xv * a.y; acc[2] += xv * a.z; acc[3] += xv * a.w;
        acc[4] += xv * b.x; acc[5] += xv * b.y; acc[6] += xv * b.z; acc[7] += xv * b.w;
    }
#pragma unroll
    for (int o = 16; o > 0; o >>= 1)
#pragma unroll
        for (int k = 0; k < 8; k++) acc[k] += __shfl_xor_sync(0xffffffffu, acc[k], o);

    if (lane == 0) {
#pragma unroll
        for (int k = 0; k < 8; k++) logits_out[(size_t)t * NEXP + k] = acc[k];
        int i0 = 0; float v0 = acc[0];
#pragma unroll
        for (int k = 1; k < 8; k++) if (acc[k] > v0) { v0 = acc[k]; i0 = k; }
        int i1 = -1; float v1 = -3.4e38f;
#pragma unroll
        for (int k = 0; k < 8; k++) if (k != i0 && acc[k] > v1) { v1 = acc[k]; i1 = k; }
        float w0 = 1.f / (1.f + __expf(v1 - v0));
        float w1 = 1.f - w0;
        int p0 = atomicAdd(&g_cnt[i0], 1);
        g_tok[i0 * TOKS + p0] = t; g_slot[i0 * TOKS + p0] = 0; g_wt[i0 * TOKS + p0] = w0;
        int p1 = atomicAdd(&g_cnt[i1], 1);
        g_tok[i1 * TOKS + p1] = t; g_slot[i1 * TOKS + p1] = 1; g_wt[i1 * TOKS + p1] = w1;
    }
}

__global__ void moe_zero() { if (threadIdx.x < NEXP) g_cnt[threadIdx.x] = 0; }

__global__ void moe_offsets() {
    int s = 0;
    for (int e = 0; e < NEXP; e++) { g_off[e] = s; s += g_cnt[e]; }
}

// ---------------- fused gate+up GEMM (fp16 in, fp32 acc) ----------------
// BM=128, BN=64 per side, BK=32. smem halves pitch 40 (conflict-free frag LDS).
// Stage: A 128x40x2=10240B, Bg 64x40x2=5120B, Bu 5120B = 20480B. 4 stages = 81920B.
__global__ void __launch_bounds__(256, 2)
moe_gateup() {
    int e = blockIdx.z;
    int cnt = g_cnt[e];
    int base = blockIdx.y * 128;
    if (base >= cnt) return;
    int n0 = blockIdx.x * 64;
    int off = g_off[e];
    const __half* wge = g_wg16 + (size_t)e * FDIM * HDIM;
    const __half* wue = g_wu16 + (size_t)e * FDIM * HDIM;

    extern __shared__ char smem8[];
    uint32_t su = smem_u32(smem8);
    const uint32_t STG = 20480;

    int tid = threadIdx.x, lane = tid & 31;
    int gid = lane >> 2, tig = lane & 3;
    int wid = tid >> 5, wm = wid >> 2, wn = wid & 3;

    // A: 128 rows x 4 chunks(16B) -> 2/thread
    const __half* asrc[2]; uint32_t asz[2], adst[2];
#pragma unroll
    for (int j = 0; j < 2; j++) {
        int idx = tid + j * 256;
        int row = idx >> 2, c = idx & 3;
        int r = base + row;
        bool v = r < cnt;
        int tok = v ? g_tok[e * TOKS + r] : 0;
        asrc[j] = g_x16 + (size_t)tok * HDIM + c * 8;
        asz[j] = v ? 16u : 0u;
        adst[j] = (uint32_t)(row * 80 + c * 16);
    }
    // B per side: 64 rows x 4 chunks -> 1/thread
    int bn = tid >> 2, bc = tid & 3;
    const __half* gsrc = wge + (size_t)(n0 + bn) * HDIM + bc * 8;
    const __half* usrc = wue + (size_t)(n0 + bn) * HDIM + bc * 8;
    uint32_t bdst = (uint32_t)(bn * 80 + bc * 16);

    float accG[4][2][4], accU[4][2][4];
#pragma unroll
    for (int m = 0; m < 4; m++)
#pragma unroll
        for (int n = 0; n < 2; n++)
#pragma unroll
            for (int q = 0; q < 4; q++) { accG[m][n][q] = 0.f; accU[m][n][q] = 0.f; }

    const int KI = HDIM / 32;  // 32

#define GU_ISSUE(s, k0)                                                  \
    do {                                                                 \
        uint32_t ab = su + (uint32_t)(s) * STG;                          \
        _Pragma("unroll") for (int j = 0; j < 2; j++)                    \
            CP16(ab + adst[j], asrc[j] + (k0), asz[j]);                  \
        CP16(ab + 10240u + bdst, gsrc + (k0), 16u);                      \
        CP16(ab + 15360u + bdst, usrc + (k0), 16u);                      \
        CP_COMMIT();                                                     \
    } while (0)

    GU_ISSUE(0, 0);
    GU_ISSUE(1, 32);
    GU_ISSUE(2, 64);

    for (int i = 0; i < KI; i++) {
        if (i <= KI - 3) CP_WAITG2();
        else if (i == KI - 2) CP_WAITG1();
        else CP_WAIT0();
        __syncthreads();
        if (i + 3 < KI) GU_ISSUE((i + 3) & 3, (i + 3) * 32);
        int sC = i & 3;
        const __half* As = reinterpret_cast<const __half*>(smem8 + sC * STG);
        const __half* Bg = reinterpret_cast<const __half*>(smem8 + sC * STG + 10240);
        const __half* Bu = reinterpret_cast<const __half*>(smem8 + sC * STG + 15360);
#pragma unroll
        for (int kk = 0; kk < 2; kk++) {
            int ko = kk * 16;
            uint32_t af[4][4];
#pragma unroll
            for (int m = 0; m < 4; m++) {
                const __half* p = As + (wm * 64 + m * 16 + gid) * 40 + 2 * tig + ko;
                af[m][0] = *reinterpret_cast<const uint32_t*>(p);
                af[m][1] = *reinterpret_cast<const uint32_t*>(p + 320);
                af[m][2] = *reinterpret_cast<const uint32_t*>(p + 8);
                af[m][3] = *reinterpret_cast<const uint32_t*>(p + 328);
            }
            uint32_t bg[2][2], bu[2][2];
#pragma unroll
            for (int n = 0; n < 2; n++) {
                const __half* q = Bg + (wn * 16 + n * 8 + gid) * 40 + 2 * tig + ko;
                bg[n][0] = *reinterpret_cast<const uint32_t*>(q);
                bg[n][1] = *reinterpret_cast<const uint32_t*>(q + 8);
                const __half* r2 = Bu + (wn * 16 + n * 8 + gid) * 40 + 2 * tig + ko;
                bu[n][0] = *reinterpret_cast<const uint32_t*>(r2);
                bu[n][1] = *reinterpret_cast<const uint32_t*>(r2 + 8);
            }
#pragma unroll
            for (int m = 0; m < 4; m++)
#pragma unroll
                for (int n = 0; n < 2; n++) {
                    mma16(accG[m][n], af[m], bg[n]);
                    mma16(accU[m][n], af[m], bu[n]);
                }
        }
    }
#undef GU_ISSUE

    // epilogue: g_h16 = fp16(silu(g) * u)
#pragma unroll
    for (int m = 0; m < 4; m++) {
#pragma unroll
        for (int half = 0; half < 2; half++) {
            int R = wm * 64 + m * 16 + gid + half * 8;
            int r = base + R;
            if (r >= cnt) continue;
            size_t rb = (size_t)(off + r) * FDIM + n0;
#pragma unroll
            for (int n = 0; n < 2; n++) {
                int col = wn * 16 + n * 8 + 2 * tig;
                float h0 = silu(accG[m][n][half * 2 + 0]) * accU[m][n][half * 2 + 0];
                float h1 = silu(accG[m][n][half * 2 + 1]) * accU[m][n][half * 2 + 1];
                *reinterpret_cast<__half2*>(g_h16 + rb + col) = __floats2half2_rn(h0, h1);
            }
        }
    }
}

// ---------------- down GEMM: y[slot][tok] = w * (g_h16 @ Wd) ----------------
// BM=128, BN=128, BK=32. Stage: A 10240B + B 128x40x2=10240B = 20480B. 4 stages.
__global__ void __launch_bounds__(256, 2)
moe_down() {
    int e = blockIdx.z;
    int cnt = g_cnt[e];
    int base = blockIdx.y * 128;
    if (base >= cnt) return;
    int n0 = blockIdx.x * 128;
    int off = g_off[e];
    const __half* wde = g_wd16 + (size_t)e * HDIM * FDIM;

    extern __shared__ char smem8[];
    uint32_t su = smem_u32(smem8);
    const uint32_t STG = 20480;

    int tid = threadIdx.x, lane = tid & 31;
    int gid = lane >> 2, tig = lane & 3;
    int wid = tid >> 5, wm = wid >> 2, wn = wid & 3;

    const __half* asrc[2]; uint32_t asz[2], adst[2];
#pragma unroll
    for (int j = 0; j < 2; j++) {
        int idx = tid + j * 256;
        int row = idx >> 2, c = idx & 3;
        int r = base + row;
        bool v = r < cnt;
        size_t arow = v ? (size_t)(off + r) : 0;
        asrc[j] = g_h16 + arow * FDIM + c * 8;
        asz[j] = v ? 16u : 0u;
        adst[j] = (uint32_t)(row * 80 + c * 16);
    }
    const __half* bsrc[2]; uint32_t bdst[2];
#pragma unroll
    for (int j = 0; j < 2; j++) {
        int idx = tid + j * 256;
        int n = idx >> 2, c = idx & 3;
        bsrc[j] = wde + (size_t)(n0 + n) * FDIM + c * 8;
        bdst[j] = (uint32_t)(n * 80 + c * 16);
    }

    float acc[4][4][4];
#pragma unroll
    for (int m = 0; m < 4; m++)
#pragma unroll
        for (int n = 0; n < 4; n++)
#pragma unroll
            for (int q = 0; q < 4; q++) acc[m][n][q] = 0.f;

    const int KI = FDIM / 32;  // 128

#define DN_ISSUE(s, k0)                                                  \
    do {                                                                 \
        uint32_t ab = su + (uint32_t)(s) * STG;                          \
        _Pragma("unroll") for (int j = 0; j < 2; j++)                    \
            CP16(ab + adst[j], asrc[j] + (k0), asz[j]);                  \
        _Pragma("unroll") for (int j = 0; j < 2; j++)                    \
            CP16(ab + 10240u + bdst[j], bsrc[j] + (k0), 16u);            \
        CP_COMMIT();                                                     \
    } while (0)

    DN_ISSUE(0, 0);
    DN_ISSUE(1, 32);
    DN_ISSUE(2, 64);

    for (int i = 0; i < KI; i++) {
        if (i <= KI - 3) CP_WAITG2();
        else if (i == KI - 2) CP_WAITG1();
        else CP_WAIT0();
        __syncthreads();
        if (i + 3 < KI) DN_ISSUE((i + 3) & 3, (i + 3) * 32);
        int sC = i & 3;
        const __half* As = reinterpret_cast<const __half*>(smem8 + sC * STG);
        const __half* Bs = reinterpret_cast<const __half*>(smem8 + sC * STG + 10240);
#pragma unroll
        for (int kk = 0; kk < 2; kk++) {
            int ko = kk * 16;
            uint32_t af[4][4];
#pragma unroll
            for (int m = 0; m < 4; m++) {
                const __half* p = As + (wm * 64 + m * 16 + gid) * 40 + 2 * tig + ko;
                af[m][0] = *reinterpret_cast<const uint32_t*>(p);
                af[m][1] = *reinterpret_cast<const uint32_t*>(p + 320);
                af[m][2] = *reinterpret_cast<const uint32_t*>(p + 8);
                af[m][3] = *reinterpret_cast<const uint32_t*>(p + 328);
            }
            uint32_t bf[4][2];
#pragma unroll
            for (int n = 0; n < 4; n++) {
                const __half* q = Bs + (wn * 32 + n * 8 + gid) * 40 + 2 * tig + ko;
                bf[n][0] = *reinterpret_cast<const uint32_t*>(q);
                bf[n][1] = *reinterpret_cast<const uint32_t*>(q + 8);
            }
#pragma unroll
            for (int m = 0; m < 4; m++)
#pragma unroll
                for (int n = 0; n < 4; n++) mma16(acc[m][n], af[m], bf[n]);
        }
    }
#undef DN_ISSUE

    // epilogue: weighted scatter
#pragma unroll
    for (int m = 0; m < 4; m++) {
#pragma unroll
        for (int half = 0; half < 2; half++) {
            int R = wm * 64 + m * 16 + gid + half * 8;
            int r = base + R;
            if (r >= cnt) continue;
            int t = g_tok[e * TOKS + r];
            int sl = g_slot[e * TOKS + r];
            float w = g_wt[e * TOKS + r];
            size_t yb = ((size_t)sl * TOKS + t) * HDIM + n0;
#pragma unroll
            for (int n = 0; n < 4; n++) {
                int col = wn * 32 + n * 8 + 2 * tig;
                float v0 = acc[m][n][half * 2 + 0], v1 = acc[m][n][half * 2 + 1];
                *reinterpret_cast<float2*>(g_y + yb + col) = make_float2(w * v0, w * v1);
            }
        }
    }
}

// ---------------- combine: out = y[slot0] + y[slot1] ----------------
__global__ void moe_combine(float* __restrict__ out) {
    size_t i = (size_t)blockIdx.x * 256 + threadIdx.x;
    const float4* y0 = reinterpret_cast<const float4*>(g_y);
    const float4* y1 = y0 + (size_t)TOKS * HDIM / 4;
    float4 a = y0[i], b = y1[i];
    reinterpret_cast<float4*>(out)[i] = make_float4(a.x + b.x, a.y + b.y, a.z + b.z, a.w + b.w);
}

// ---------------- launch ----------------
extern "C" void kernel_launch(void* const* d_in, const int* in_sizes, int n_in,
                              void* d_out, int out_size) {
    const float* x   = (const float*)d_in[0];
    const float* wg  = (const float*)d_in[1];
    const float* wgp = (const float*)d_in[2];
    const float* wup = (const float*)d_in[3];
    const float* wdp = (const float*)d_in[4];
    float* out = (float*)d_out;

    cudaFuncSetAttribute(moe_gateup, cudaFuncAttributeMaxDynamicSharedMemorySize, 81920);
    cudaFuncSetAttribute(moe_down,   cudaFuncAttributeMaxDynamicSharedMemorySize, 81920);

    moe_zero<<<1, 32>>>();
    moe_router<<<TOKS / 8, 256>>>(x, wg, out + (size_t)TOKS * HDIM);
    moe_offsets<<<1, 1>>>();
    conv_x<<<(TOKS * HDIM / 8) / 256, 256>>>(x);
    {
        __half* dwg; cudaGetSymbolAddress((void**)&dwg, g_wg16);
        __half* dwu; cudaGetSymbolAddress((void**)&dwu, g_wu16);
        __half* dwd; cudaGetSymbolAddress((void**)&dwd, g_wd16);
        conv_w<<<dim3(FDIM / 64, HDIM / 64, NEXP), 256>>>(wgp, dwg, HDIM, FDIM);
        conv_w<<<dim3(FDIM / 64, HDIM / 64, NEXP), 256>>>(wup, dwu, HDIM, FDIM);
        conv_w<<<dim3(HDIM / 64, FDIM / 64, NEXP), 256>>>(wdp, dwd, FDIM, HDIM);
    }
    moe_gateup<<<dim3(FDIM / 64, TOKS / 128, NEXP), 256, 81920>>>();
    moe_down<<<dim3(HDIM / 128, TOKS / 128, NEXP), 256, 81920>>>();
    moe_combine<<<(TOKS * HDIM / 4) / 256, 256>>>(out);
}

// round 8
// speedup vs baseline: 2.2167x; 1.0988x over previous
#include <cuda_runtime.h>
#include <cuda_fp16.h>
#include <cstdint>

#define TOKS 8192
#define HDIM 1024
#define FDIM 4096
#define NEXP 8

// ---------------- scratch (__device__ globals; no allocation) ----------------
__device__ int    g_cnt[NEXP];
__device__ int    g_off[NEXP];
__device__ int    g_tok[NEXP * TOKS];
__device__ int    g_slot[NEXP * TOKS];
__device__ float  g_wt[NEXP * TOKS];
__device__ __half g_x16[(size_t)TOKS * HDIM];            // fp16 x (16 MB)
__device__ __half g_wg16[(size_t)NEXP * FDIM * HDIM];    // gate W, [e][n][k] (64 MB)
__device__ __half g_wu16[(size_t)NEXP * FDIM * HDIM];    // up   W, [e][n][k] (64 MB)
__device__ __half g_wd16[(size_t)NEXP * HDIM * FDIM];    // down W, [e][n][k] (64 MB)
__device__ __half g_h16[(size_t)2 * TOKS * FDIM];        // hidden (128 MB)
__device__ float  g_y[(size_t)2 * TOKS * HDIM];          // slot outputs (64 MB)

// ---------------- helpers ----------------
static __device__ __forceinline__ uint32_t smem_u32(const void* p) {
    uint32_t a;
    asm("{ .reg .u64 t; cvta.to.shared.u64 t, %1; cvt.u32.u64 %0, t; }" : "=r"(a) : "l"(p));
    return a;
}
static __device__ __forceinline__ void mma16(float* c, const uint32_t* a, const uint32_t* b) {
    asm volatile(
        "mma.sync.aligned.m16n8k16.row.col.f32.f16.f16.f32 "
        "{%0,%1,%2,%3}, {%4,%5,%6,%7}, {%8,%9}, {%0,%1,%2,%3};"
        : "+f"(c[0]), "+f"(c[1]), "+f"(c[2]), "+f"(c[3])
        : "r"(a[0]), "r"(a[1]), "r"(a[2]), "r"(a[3]), "r"(b[0]), "r"(b[1]));
}
#define LDSM4(r0, r1, r2, r3, addr)                                              \
    asm volatile("ldmatrix.sync.aligned.m8n8.x4.shared.b16 {%0,%1,%2,%3}, [%4];" \
                 : "=r"(r0), "=r"(r1), "=r"(r2), "=r"(r3) : "r"(addr))
#define CP16(dst, src, sz) \
    asm volatile("cp.async.cg.shared.global [%0], [%1], 16, %2;\n" ::"r"(dst), "l"(src), "r"(sz))
#define CP_COMMIT() asm volatile("cp.async.commit_group;\n" ::: "memory")
#define CP_WAITG2() asm volatile("cp.async.wait_group 2;\n" ::: "memory")
#define CP_WAITG1() asm volatile("cp.async.wait_group 1;\n" ::: "memory")
#define CP_WAIT0()  asm volatile("cp.async.wait_group 0;\n" ::: "memory")

static __device__ __forceinline__ float silu(float v) { return v / (1.f + __expf(-v)); }

// ---------------- convert x -> fp16 ----------------
__global__ void conv_x(const float* __restrict__ x) {
    size_t i = ((size_t)blockIdx.x * 256 + threadIdx.x) * 8;
    float4 a = *reinterpret_cast<const float4*>(x + i);
    float4 b = *reinterpret_cast<const float4*>(x + i + 4);
    __half2 h[4];
    h[0] = __floats2half2_rn(a.x, a.y);
    h[1] = __floats2half2_rn(a.z, a.w);
    h[2] = __floats2half2_rn(b.x, b.y);
    h[3] = __floats2half2_rn(b.z, b.w);
    *reinterpret_cast<uint4*>(g_x16 + i) = *reinterpret_cast<uint4*>(h);
}

// ---------------- convert+transpose W: [e][k][n] fp32 -> [e][n][k] fp16 ----------------
__global__ void conv_w(const float* __restrict__ src, __half* __restrict__ dst,
                       int Kd, int Nd) {
    __shared__ float t[64][65];
    int e = blockIdx.z;
    int k0 = blockIdx.y * 64, n0 = blockIdx.x * 64;
    const float* S = src + ((size_t)e * Kd + k0) * Nd + n0;
    int tid = threadIdx.x;
    int kr = tid >> 4, nc = (tid & 15) * 4;
#pragma unroll
    for (int j = 0; j < 4; j++) {
        float4 v = *reinterpret_cast<const float4*>(S + (size_t)(kr + j * 16) * Nd + nc);
        t[kr + j * 16][nc + 0] = v.x;
        t[kr + j * 16][nc + 1] = v.y;
        t[kr + j * 16][nc + 2] = v.z;
        t[kr + j * 16][nc + 3] = v.w;
    }
    __syncthreads();
    int nr = tid >> 2, kc = (tid & 3) * 16;
    __half hb[16];
#pragma unroll
    for (int q = 0; q < 16; q++) hb[q] = __float2half_rn(t[kc + q][nr]);
    __half* D = dst + ((size_t)e * Nd + n0 + nr) * Kd + k0 + kc;
    *reinterpret_cast<uint4*>(D)     = *reinterpret_cast<uint4*>(hb);
    *reinterpret_cast<uint4*>(D + 8) = *reinterpret_cast<uint4*>(hb + 8);
}

// ---------------- router ----------------
__global__ void moe_router(const float* __restrict__ x, const float* __restrict__ wg,
                           float* __restrict__ logits_out) {
    int t = blockIdx.x * 8 + (threadIdx.x >> 5);
    int lane = threadIdx.x & 31;
    const float* xr = x + (size_t)t * HDIM;
    float acc[8] = {0.f, 0.f, 0.f, 0.f, 0.f, 0.f, 0.f, 0.f};
    for (int j = lane; j < HDIM; j += 32) {
        float xv = xr[j];
        const float4* w4 = reinterpret_cast<const float4*>(wg + (size_t)j * NEXP);
        float4 a = w4[0], b = w4[1];
        acc[0] += xv * a.x; acc[1] += xv * a.y; acc[2] += xv * a.z; acc[3] += xv * a.w;
        acc[4] += xv * b.x; acc[5] += xv * b.y; acc[6] += xv * b.z; acc[7] += xv * b.w;
    }
#pragma unroll
    for (int o = 16; o > 0; o >>= 1)
#pragma unroll
        for (int k = 0; k < 8; k++) acc[k] += __shfl_xor_sync(0xffffffffu, acc[k], o);

    if (lane == 0) {
#pragma unroll
        for (int k = 0; k < 8; k++) logits_out[(size_t)t * NEXP + k] = acc[k];
        int i0 = 0; float v0 = acc[0];
#pragma unroll
        for (int k = 1; k < 8; k++) if (acc[k] > v0) { v0 = acc[k]; i0 = k; }
        int i1 = -1; float v1 = -3.4e38f;
#pragma unroll
        for (int k = 0; k < 8; k++) if (k != i0 && acc[k] > v1) { v1 = acc[k]; i1 = k; }
        float w0 = 1.f / (1.f + __expf(v1 - v0));
        float w1 = 1.f - w0;
        int p0 = atomicAdd(&g_cnt[i0], 1);
        g_tok[i0 * TOKS + p0] = t; g_slot[i0 * TOKS + p0] = 0; g_wt[i0 * TOKS + p0] = w0;
        int p1 = atomicAdd(&g_cnt[i1], 1);
        g_tok[i1 * TOKS + p1] = t; g_slot[i1 * TOKS + p1] = 1; g_wt[i1 * TOKS + p1] = w1;
    }
}

__global__ void moe_zero() { if (threadIdx.x < NEXP) g_cnt[threadIdx.x] = 0; }

__global__ void moe_offsets() {
    int s = 0;
    for (int e = 0; e < NEXP; e++) { g_off[e] = s; s += g_cnt[e]; }
}

// ---------------- fused gate+up GEMM (fp16, ldmatrix fragment loads) ----------------
// BM=128, BN=64 per side, BK=32, pitch 40 halves. Stage 20480B, 4 stages = 81920B.
__global__ void __launch_bounds__(256, 2)
moe_gateup() {
    int e = blockIdx.z;
    int cnt = g_cnt[e];
    int base = blockIdx.y * 128;
    if (base >= cnt) return;
    int n0 = blockIdx.x * 64;
    int off = g_off[e];
    const __half* wge = g_wg16 + (size_t)e * FDIM * HDIM;
    const __half* wue = g_wu16 + (size_t)e * FDIM * HDIM;

    extern __shared__ char smem8[];
    uint32_t su = smem_u32(smem8);
    const uint32_t STG = 20480;

    int tid = threadIdx.x, lane = tid & 31;
    int gid = lane >> 2, tig = lane & 3;
    int wid = tid >> 5, wm = wid >> 2, wn = wid & 3;

    // cp.async descriptors
    const __half* asrc[2]; uint32_t asz[2], adst[2];
#pragma unroll
    for (int j = 0; j < 2; j++) {
        int idx = tid + j * 256;
        int row = idx >> 2, c = idx & 3;
        int r = base + row;
        bool v = r < cnt;
        int tok = v ? g_tok[e * TOKS + r] : 0;
        asrc[j] = g_x16 + (size_t)tok * HDIM + c * 8;
        asz[j] = v ? 16u : 0u;
        adst[j] = (uint32_t)(row * 80 + c * 16);
    }
    int bn = tid >> 2, bc = tid & 3;
    const __half* gsrc = wge + (size_t)(n0 + bn) * HDIM + bc * 8;
    const __half* usrc = wue + (size_t)(n0 + bn) * HDIM + bc * 8;
    uint32_t bdst = (uint32_t)(bn * 80 + bc * 16);

    // ldmatrix per-lane byte offsets (within a stage)
    uint32_t aoff[4];
#pragma unroll
    for (int m = 0; m < 4; m++)
        aoff[m] = (uint32_t)(((wm * 64 + m * 16 + (lane & 15)) * 40 + (lane >> 4) * 8) * 2);
    // B pair (covers both n-frags of this warp's 16-wide slice)
    uint32_t boff = (uint32_t)(((wn * 16 + (lane & 7) + ((lane >> 4) & 1) * 8) * 40 +
                                ((lane >> 3) & 1) * 8) * 2);

    float accG[4][2][4], accU[4][2][4];
#pragma unroll
    for (int m = 0; m < 4; m++)
#pragma unroll
        for (int n = 0; n < 2; n++)
#pragma unroll
            for (int q = 0; q < 4; q++) { accG[m][n][q] = 0.f; accU[m][n][q] = 0.f; }

    const int KI = HDIM / 32;  // 32

#define GU_ISSUE(s, k0)                                                  \
    do {                                                                 \
        uint32_t ab = su + (uint32_t)(s) * STG;                          \
        _Pragma("unroll") for (int j = 0; j < 2; j++)                    \
            CP16(ab + adst[j], asrc[j] + (k0), asz[j]);                  \
        CP16(ab + 10240u + bdst, gsrc + (k0), 16u);                      \
        CP16(ab + 15360u + bdst, usrc + (k0), 16u);                      \
        CP_COMMIT();                                                     \
    } while (0)

    GU_ISSUE(0, 0);
    GU_ISSUE(1, 32);
    GU_ISSUE(2, 64);

    for (int i = 0; i < KI; i++) {
        if (i <= KI - 3) CP_WAITG2();
        else if (i == KI - 2) CP_WAITG1();
        else CP_WAIT0();
        __syncthreads();
        if (i + 3 < KI) GU_ISSUE((i + 3) & 3, (i + 3) * 32);
        uint32_t ab = su + (uint32_t)(i & 3) * STG;
#pragma unroll
        for (int kk = 0; kk < 2; kk++) {
            uint32_t kb = (uint32_t)(kk * 32);  // 16 halves
            uint32_t af[4][4], bg[4], bu[4];
#pragma unroll
            for (int m = 0; m < 4; m++)
                LDSM4(af[m][0], af[m][1], af[m][2], af[m][3], ab + aoff[m] + kb);
            LDSM4(bg[0], bg[1], bg[2], bg[3], ab + 10240u + boff + kb);
            LDSM4(bu[0], bu[1], bu[2], bu[3], ab + 15360u + boff + kb);
#pragma unroll
            for (int m = 0; m < 4; m++)
#pragma unroll
                for (int n = 0; n < 2; n++) {
                    mma16(accG[m][n], af[m], bg + n * 2);
                    mma16(accU[m][n], af[m], bu + n * 2);
                }
        }
    }
#undef GU_ISSUE

    // epilogue: g_h16 = fp16(silu(g) * u)
#pragma unroll
    for (int m = 0; m < 4; m++) {
#pragma unroll
        for (int half = 0; half < 2; half++) {
            int R = wm * 64 + m * 16 + gid + half * 8;
            int r = base + R;
            if (r >= cnt) continue;
            size_t rb = (size_t)(off + r) * FDIM + n0;
#pragma unroll
            for (int n = 0; n < 2; n++) {
                int col = wn * 16 + n * 8 + 2 * tig;
                float h0 = silu(accG[m][n][half * 2 + 0]) * accU[m][n][half * 2 + 0];
                float h1 = silu(accG[m][n][half * 2 + 1]) * accU[m][n][half * 2 + 1];
                *reinterpret_cast<__half2*>(g_h16 + rb + col) = __floats2half2_rn(h0, h1);
            }
        }
    }
}

// ---------------- down GEMM: y[slot][tok] = w * (g_h16 @ Wd), ldmatrix loads ----------------
__global__ void __launch_bounds__(256, 2)
moe_down() {
    int e = blockIdx.z;
    int cnt = g_cnt[e];
    int base = blockIdx.y * 128;
    if (base >= cnt) return;
    int n0 = blockIdx.x * 128;
    int off = g_off[e];
    const __half* wde = g_wd16 + (size_t)e * HDIM * FDIM;

    extern __shared__ char smem8[];
    uint32_t su = smem_u32(smem8);
    const uint32_t STG = 20480;

    int tid = threadIdx.x, lane = tid & 31;
    int gid = lane >> 2, tig = lane & 3;
    int wid = tid >> 5, wm = wid >> 2, wn = wid & 3;

    const __half* asrc[2]; uint32_t asz[2], adst[2];
#pragma unroll
    for (int j = 0; j < 2; j++) {
        int idx = tid + j * 256;
        int row = idx >> 2, c = idx & 3;
        int r = base + row;
        bool v = r < cnt;
        size_t arow = v ? (size_t)(off + r) : 0;
        asrc[j] = g_h16 + arow * FDIM + c * 8;
        asz[j] = v ? 16u : 0u;
        adst[j] = (uint32_t)(row * 80 + c * 16);
    }
    const __half* bsrc[2]; uint32_t bdst[2];
#pragma unroll
    for (int j = 0; j < 2; j++) {
        int idx = tid + j * 256;
        int n = idx >> 2, c = idx & 3;
        bsrc[j] = wde + (size_t)(n0 + n) * FDIM + c * 8;
        bdst[j] = (uint32_t)(n * 80 + c * 16);
    }

    uint32_t aoff[4];
#pragma unroll
    for (int m = 0; m < 4; m++)
        aoff[m] = (uint32_t)(((wm * 64 + m * 16 + (lane & 15)) * 40 + (lane >> 4) * 8) * 2);
    uint32_t boff[2];
#pragma unroll
    for (int p = 0; p < 2; p++)
        boff[p] = (uint32_t)(((wn * 32 + p * 16 + (lane & 7) + ((lane >> 4) & 1) * 8) * 40 +
                              ((lane >> 3) & 1) * 8) * 2);

    float acc[4][4][4];
#pragma unroll
    for (int m = 0; m < 4; m++)
#pragma unroll
        for (int n = 0; n < 4; n++)
#pragma unroll
            for (int q = 0; q < 4; q++) acc[m][n][q] = 0.f;

    const int KI = FDIM / 32;  // 128

#define DN_ISSUE(s, k0)                                                  \
    do {                                                                 \
        uint32_t ab = su + (uint32_t)(s) * STG;                          \
        _Pragma("unroll") for (int j = 0; j < 2; j++)                    \
            CP16(ab + adst[j], asrc[j] + (k0), asz[j]);                  \
        _Pragma("unroll") for (int j = 0; j < 2; j++)                    \
            CP16(ab + 10240u + bdst[j], bsrc[j] + (k0), 16u);            \
        CP_COMMIT();                                                     \
    } while (0)

    DN_ISSUE(0, 0);
    DN_ISSUE(1, 32);
    DN_ISSUE(2, 64);

    for (int i = 0; i < KI; i++) {
        if (i <= KI - 3) CP_WAITG2();
        else if (i == KI - 2) CP_WAITG1();
        else CP_WAIT0();
        __syncthreads();
        if (i + 3 < KI) DN_ISSUE((i + 3) & 3, (i + 3) * 32);
        uint32_t ab = su + (uint32_t)(i & 3) * STG;
#pragma unroll
        for (int kk = 0; kk < 2; kk++) {
            uint32_t kb = (uint32_t)(kk * 32);
            uint32_t af[4][4], bf[2][4];
#pragma unroll
            for (int m = 0; m < 4; m++)
                LDSM4(af[m][0], af[m][1], af[m][2], af[m][3], ab + aoff[m] + kb);
#pragma unroll
            for (int p = 0; p < 2; p++)
                LDSM4(bf[p][0], bf[p][1], bf[p][2], bf[p][3], ab + 10240u + boff[p] + kb);
#pragma unroll
            for (int m = 0; m < 4; m++)
#pragma unroll
                for (int n = 0; n < 4; n++)
                    mma16(acc[m][n], af[m], bf[n >> 1] + (n & 1) * 2);
        }
    }
#undef DN_ISSUE

    // epilogue: weighted scatter
#pragma unroll
    for (int m = 0; m < 4; m++) {
#pragma unroll
        for (int half = 0; half < 2; half++) {
            int R = wm * 64 + m * 16 + gid + half * 8;
            int r = base + R;
            if (r >= cnt) continue;
            int t = g_tok[e * TOKS + r];
            int sl = g_slot[e * TOKS + r];
            float w = g_wt[e * TOKS + r];
            size_t yb = ((size_t)sl * TOKS + t) * HDIM + n0;
#pragma unroll
            for (int n = 0; n < 4; n++) {
                int col = wn * 32 + n * 8 + 2 * tig;
                float v0 = acc[m][n][half * 2 + 0], v1 = acc[m][n][half * 2 + 1];
                *reinterpret_cast<float2*>(g_y + yb + col) = make_float2(w * v0, w * v1);
            }
        }
    }
}

// ---------------- combine: out = y[slot0] + y[slot1] ----------------
__global__ void moe_combine(float* __restrict__ out) {
    size_t i = (size_t)blockIdx.x * 256 + threadIdx.x;
    const float4* y0 = reinterpret_cast<const float4*>(g_y);
    const float4* y1 = y0 + (size_t)TOKS * HDIM / 4;
    float4 a = y0[i], b = y1[i];
    reinterpret_cast<float4*>(out)[i] = make_float4(a.x + b.x, a.y + b.y, a.z + b.z, a.w + b.w);
}

// ---------------- launch ----------------
extern "C" void kernel_launch(void* const* d_in, const int* in_sizes, int n_in,
                              void* d_out, int out_size) {
    const float* x   = (const float*)d_in[0];
    const float* wg  = (const float*)d_in[1];
    const float* wgp = (const float*)d_in[2];
    const float* wup = (const float*)d_in[3];
    const float* wdp = (const float*)d_in[4];
    float* out = (float*)d_out;

    cudaFuncSetAttribute(moe_gateup, cudaFuncAttributeMaxDynamicSharedMemorySize, 81920);
    cudaFuncSetAttribute(moe_down,   cudaFuncAttributeMaxDynamicSharedMemorySize, 81920);

    moe_zero<<<1, 32>>>();
    moe_router<<<TOKS / 8, 256>>>(x, wg, out + (size_t)TOKS * HDIM);
    moe_offsets<<<1, 1>>>();
    conv_x<<<(TOKS * HDIM / 8) / 256, 256>>>(x);
    {
        __half* dwg; cudaGetSymbolAddress((void**)&dwg, g_wg16);
        __half* dwu; cudaGetSymbolAddress((void**)&dwu, g_wu16);
        __half* dwd; cudaGetSymbolAddress((void**)&dwd, g_wd16);
        conv_w<<<dim3(FDIM / 64, HDIM / 64, NEXP), 256>>>(wgp, dwg, HDIM, FDIM);
        conv_w<<<dim3(FDIM / 64, HDIM / 64, NEXP), 256>>>(wup, dwu, HDIM, FDIM);
        conv_w<<<dim3(HDIM / 64, FDIM / 64, NEXP), 256>>>(wdp, dwd, FDIM, HDIM);
    }
    moe_gateup<<<dim3(FDIM / 64, TOKS / 128, NEXP), 256, 81920>>>();
    moe_down<<<dim3(HDIM / 128, TOKS / 128, NEXP), 256, 81920>>>();
    moe_combine<<<(TOKS * HDIM / 4) / 256, 256>>>(out);
}

// round 9
// speedup vs baseline: 2.2556x; 1.0176x over previous
#include <cuda_runtime.h>
#include <cuda_fp16.h>
#include <cstdint>

#define TOKS 8192
#define HDIM 1024
#define FDIM 4096
#define NEXP 8

// ---------------- scratch (__device__ globals; no allocation) ----------------
__device__ int    g_cnt[NEXP];
__device__ int    g_tok[NEXP * TOKS];
__device__ int    g_slot[NEXP * TOKS];
__device__ float  g_wt[NEXP * TOKS];
__device__ __half g_x16[(size_t)TOKS * HDIM];            // fp16 x (16 MB)
__device__ __half g_wg16[(size_t)NEXP * FDIM * HDIM];    // gate W, [e][n][k] (64 MB)
__device__ __half g_wu16[(size_t)NEXP * FDIM * HDIM];    // up   W, [e][n][k] (64 MB)
__device__ __half g_wd16[(size_t)NEXP * HDIM * FDIM];    // down W, [e][n][k] (64 MB)
__device__ __half g_h16[(size_t)2 * TOKS * FDIM];        // hidden (128 MB)
__device__ float  g_y[(size_t)2 * TOKS * HDIM];          // slot outputs (64 MB)

// ---------------- helpers ----------------
static __device__ __forceinline__ uint32_t smem_u32(const void* p) {
    uint32_t a;
    asm("{ .reg .u64 t; cvta.to.shared.u64 t, %1; cvt.u32.u64 %0, t; }" : "=r"(a) : "l"(p));
    return a;
}
static __device__ __forceinline__ void mma16(float* c, const uint32_t* a, const uint32_t* b) {
    asm volatile(
        "mma.sync.aligned.m16n8k16.row.col.f32.f16.f16.f32 "
        "{%0,%1,%2,%3}, {%4,%5,%6,%7}, {%8,%9}, {%0,%1,%2,%3};"
        : "+f"(c[0]), "+f"(c[1]), "+f"(c[2]), "+f"(c[3])
        : "r"(a[0]), "r"(a[1]), "r"(a[2]), "r"(a[3]), "r"(b[0]), "r"(b[1]));
}
#define LDSM4(r0, r1, r2, r3, addr)                                              \
    asm volatile("ldmatrix.sync.aligned.m8n8.x4.shared.b16 {%0,%1,%2,%3}, [%4];" \
                 : "=r"(r0), "=r"(r1), "=r"(r2), "=r"(r3) : "r"(addr))
#define CP16(dst, src, sz) \
    asm volatile("cp.async.cg.shared.global [%0], [%1], 16, %2;\n" ::"r"(dst), "l"(src), "r"(sz))
#define CP_COMMIT() asm volatile("cp.async.commit_group;\n" ::: "memory")
#define CP_WAITG3() asm volatile("cp.async.wait_group 3;\n" ::: "memory")
#define CP_WAITG2() asm volatile("cp.async.wait_group 2;\n" ::: "memory")
#define CP_WAITG1() asm volatile("cp.async.wait_group 1;\n" ::: "memory")
#define CP_WAIT0()  asm volatile("cp.async.wait_group 0;\n" ::: "memory")

static __device__ __forceinline__ float silu(float v) { return v / (1.f + __expf(-v)); }

static __device__ __forceinline__ int expert_off(int e) {
    int off = 0;
#pragma unroll
    for (int i = 0; i < NEXP; i++) if (i < e) off += g_cnt[i];
    return off;
}

// ---------------- convert x -> fp16 (also zeroes g_cnt) ----------------
__global__ void conv_x(const float* __restrict__ x) {
    if (blockIdx.x == 0 && threadIdx.x < NEXP) g_cnt[threadIdx.x] = 0;
    size_t i = ((size_t)blockIdx.x * 256 + threadIdx.x) * 8;
    float4 a = *reinterpret_cast<const float4*>(x + i);
    float4 b = *reinterpret_cast<const float4*>(x + i + 4);
    __half2 h[4];
    h[0] = __floats2half2_rn(a.x, a.y);
    h[1] = __floats2half2_rn(a.z, a.w);
    h[2] = __floats2half2_rn(b.x, b.y);
    h[3] = __floats2half2_rn(b.z, b.w);
    *reinterpret_cast<uint4*>(g_x16 + i) = *reinterpret_cast<uint4*>(h);
}

// ---------------- convert+transpose W: [e][k][n] fp32 -> [e][n][k] fp16 ----------------
__global__ void conv_w(const float* __restrict__ src, __half* __restrict__ dst,
                       int Kd, int Nd) {
    __shared__ float t[64][65];
    int e = blockIdx.z;
    int k0 = blockIdx.y * 64, n0 = blockIdx.x * 64;
    const float* S = src + ((size_t)e * Kd + k0) * Nd + n0;
    int tid = threadIdx.x;
    int kr = tid >> 4, nc = (tid & 15) * 4;
#pragma unroll
    for (int j = 0; j < 4; j++) {
        float4 v = *reinterpret_cast<const float4*>(S + (size_t)(kr + j * 16) * Nd + nc);
        t[kr + j * 16][nc + 0] = v.x;
        t[kr + j * 16][nc + 1] = v.y;
        t[kr + j * 16][nc + 2] = v.z;
        t[kr + j * 16][nc + 3] = v.w;
    }
    __syncthreads();
    int nr = tid >> 2, kc = (tid & 3) * 16;
    __half hb[16];
#pragma unroll
    for (int q = 0; q < 16; q++) hb[q] = __float2half_rn(t[kc + q][nr]);
    __half* D = dst + ((size_t)e * Nd + n0 + nr) * Kd + k0 + kc;
    *reinterpret_cast<uint4*>(D)     = *reinterpret_cast<uint4*>(hb);
    *reinterpret_cast<uint4*>(D + 8) = *reinterpret_cast<uint4*>(hb + 8);
}

// ---------------- router ----------------
__global__ void moe_router(const float* __restrict__ x, const float* __restrict__ wg,
                           float* __restrict__ logits_out) {
    int t = blockIdx.x * 8 + (threadIdx.x >> 5);
    int lane = threadIdx.x & 31;
    const float* xr = x + (size_t)t * HDIM;
    float acc[8] = {0.f, 0.f, 0.f, 0.f, 0.f, 0.f, 0.f, 0.f};
    for (int j = lane; j < HDIM; j += 32) {
        float xv = xr[j];
        const float4* w4 = reinterpret_cast<const float4*>(wg + (size_t)j * NEXP);
        float4 a = w4[0], b = w4[1];
        acc[0] += xv * a.x; acc[1] += xv * a.y; acc[2] += xv * a.z; acc[3] += xv * a.w;
        acc[4] += xv * b.x; acc[5] += xv * b.y; acc[6] += xv * b.z; acc[7] += xv * b.w;
    }
#pragma unroll
    for (int o = 16; o > 0; o >>= 1)
#pragma unroll
        for (int k = 0; k < 8; k++) acc[k] += __shfl_xor_sync(0xffffffffu, acc[k], o);

    if (lane == 0) {
#pragma unroll
        for (int k = 0; k < 8; k++) logits_out[(size_t)t * NEXP + k] = acc[k];
        int i0 = 0; float v0 = acc[0];
#pragma unroll
        for (int k = 1; k < 8; k++) if (acc[k] > v0) { v0 = acc[k]; i0 = k; }
        int i1 = -1; float v1 = -3.4e38f;
#pragma unroll
        for (int k = 0; k < 8; k++) if (k != i0 && acc[k] > v1) { v1 = acc[k]; i1 = k; }
        float w0 = 1.f / (1.f + __expf(v1 - v0));
        float w1 = 1.f - w0;
        int p0 = atomicAdd(&g_cnt[i0], 1);
        g_tok[i0 * TOKS + p0] = t; g_slot[i0 * TOKS + p0] = 0; g_wt[i0 * TOKS + p0] = w0;
        int p1 = atomicAdd(&g_cnt[i1], 1);
        g_tok[i1 * TOKS + p1] = t; g_slot[i1 * TOKS + p1] = 1; g_wt[i1 * TOKS + p1] = w1;
    }
}

// ---------------- fused gate+up GEMM (fp16, ldmatrix, 5-stage cp.async) ----------------
// BM=128, BN=64 per side, BK=32, pitch 40 halves. Stage 20480B, 5 stages = 102400B.
__global__ void __launch_bounds__(256, 2)
moe_gateup() {
    int e = blockIdx.z;
    int cnt = g_cnt[e];
    int base = blockIdx.y * 128;
    if (base >= cnt) return;
    int n0 = blockIdx.x * 64;
    int off = expert_off(e);
    const __half* wge = g_wg16 + (size_t)e * FDIM * HDIM;
    const __half* wue = g_wu16 + (size_t)e * FDIM * HDIM;

    extern __shared__ char smem8[];
    uint32_t su = smem_u32(smem8);
    const uint32_t STG = 20480;

    int tid = threadIdx.x, lane = tid & 31;
    int gid = lane >> 2, tig = lane & 3;
    int wid = tid >> 5, wm = wid >> 2, wn = wid & 3;

    // cp.async descriptors
    const __half* asrc[2]; uint32_t asz[2], adst[2];
#pragma unroll
    for (int j = 0; j < 2; j++) {
        int idx = tid + j * 256;
        int row = idx >> 2, c = idx & 3;
        int r = base + row;
        bool v = r < cnt;
        int tok = v ? g_tok[e * TOKS + r] : 0;
        asrc[j] = g_x16 + (size_t)tok * HDIM + c * 8;
        asz[j] = v ? 16u : 0u;
        adst[j] = (uint32_t)(row * 80 + c * 16);
    }
    int bn = tid >> 2, bc = tid & 3;
    const __half* gsrc = wge + (size_t)(n0 + bn) * HDIM + bc * 8;
    const __half* usrc = wue + (size_t)(n0 + bn) * HDIM + bc * 8;
    uint32_t bdst = (uint32_t)(bn * 80 + bc * 16);

    // ldmatrix per-lane byte offsets (within a stage)
    uint32_t aoff[4];
#pragma unroll
    for (int m = 0; m < 4; m++)
        aoff[m] = (uint32_t)(((wm * 64 + m * 16 + (lane & 15)) * 40 + (lane >> 4) * 8) * 2);
    uint32_t boff = (uint32_t)(((wn * 16 + (lane & 7) + ((lane >> 4) & 1) * 8) * 40 +
                                ((lane >> 3) & 1) * 8) * 2);

    float accG[4][2][4], accU[4][2][4];
#pragma unroll
    for (int m = 0; m < 4; m++)
#pragma unroll
        for (int n = 0; n < 2; n++)
#pragma unroll
            for (int q = 0; q < 4; q++) { accG[m][n][q] = 0.f; accU[m][n][q] = 0.f; }

    const int KI = HDIM / 32;  // 32

#define GU_ISSUE(s, k0)                                                  \
    do {                                                                 \
        uint32_t ab = su + (uint32_t)(s) * STG;                          \
        _Pragma("unroll") for (int j = 0; j < 2; j++)                    \
            CP16(ab + adst[j], asrc[j] + (k0), asz[j]);                  \
        CP16(ab + 10240u + bdst, gsrc + (k0), 16u);                      \
        CP16(ab + 15360u + bdst, usrc + (k0), 16u);                      \
        CP_COMMIT();                                                     \
    } while (0)

    GU_ISSUE(0, 0);
    GU_ISSUE(1, 32);
    GU_ISSUE(2, 64);
    GU_ISSUE(3, 96);

    int sC = 0, sP = 4;
    for (int i = 0; i < KI; i++) {
        if (i <= KI - 4) CP_WAITG3();
        else if (i == KI - 3) CP_WAITG2();
        else if (i == KI - 2) CP_WAITG1();
        else CP_WAIT0();
        __syncthreads();
        if (i + 4 < KI) {
            GU_ISSUE(sP, (i + 4) * 32);
            sP = (sP == 4) ? 0 : sP + 1;
        }
        uint32_t ab = su + (uint32_t)sC * STG;
        sC = (sC == 4) ? 0 : sC + 1;
#pragma unroll
        for (int kk = 0; kk < 2; kk++) {
            uint32_t kb = (uint32_t)(kk * 32);  // 16 halves
            uint32_t af[4][4], bg[4], bu[4];
#pragma unroll
            for (int m = 0; m < 4; m++)
                LDSM4(af[m][0], af[m][1], af[m][2], af[m][3], ab + aoff[m] + kb);
            LDSM4(bg[0], bg[1], bg[2], bg[3], ab + 10240u + boff + kb);
            LDSM4(bu[0], bu[1], bu[2], bu[3], ab + 15360u + boff + kb);
#pragma unroll
            for (int m = 0; m < 4; m++)
#pragma unroll
                for (int n = 0; n < 2; n++) {
                    mma16(accG[m][n], af[m], bg + n * 2);
                    mma16(accU[m][n], af[m], bu + n * 2);
                }
        }
    }
#undef GU_ISSUE

    // epilogue: g_h16 = fp16(silu(g) * u)
#pragma unroll
    for (int m = 0; m < 4; m++) {
#pragma unroll
        for (int half = 0; half < 2; half++) {
            int R = wm * 64 + m * 16 + gid + half * 8;
            int r = base + R;
            if (r >= cnt) continue;
            size_t rb = (size_t)(off + r) * FDIM + n0;
#pragma unroll
            for (int n = 0; n < 2; n++) {
                int col = wn * 16 + n * 8 + 2 * tig;
                float h0 = silu(accG[m][n][half * 2 + 0]) * accU[m][n][half * 2 + 0];
                float h1 = silu(accG[m][n][half * 2 + 1]) * accU[m][n][half * 2 + 1];
                *reinterpret_cast<__half2*>(g_h16 + rb + col) = __floats2half2_rn(h0, h1);
            }
        }
    }
}

// ---------------- down GEMM: y[slot][tok] = w * (g_h16 @ Wd), 5-stage ----------------
__global__ void __launch_bounds__(256, 2)
moe_down() {
    int e = blockIdx.z;
    int cnt = g_cnt[e];
    int base = blockIdx.y * 128;
    if (base >= cnt) return;
    int n0 = blockIdx.x * 128;
    int off = expert_off(e);
    const __half* wde = g_wd16 + (size_t)e * HDIM * FDIM;

    extern __shared__ char smem8[];
    uint32_t su = smem_u32(smem8);
    const uint32_t STG = 20480;

    int tid = threadIdx.x, lane = tid & 31;
    int gid = lane >> 2, tig = lane & 3;
    int wid = tid >> 5, wm = wid >> 2, wn = wid & 3;

    const __half* asrc[2]; uint32_t asz[2], adst[2];
#pragma unroll
    for (int j = 0; j < 2; j++) {
        int idx = tid + j * 256;
        int row = idx >> 2, c = idx & 3;
        int r = base + row;
        bool v = r < cnt;
        size_t arow = v ? (size_t)(off + r) : 0;
        asrc[j] = g_h16 + arow * FDIM + c * 8;
        asz[j] = v ? 16u : 0u;
        adst[j] = (uint32_t)(row * 80 + c * 16);
    }
    const __half* bsrc[2]; uint32_t bdst[2];
#pragma unroll
    for (int j = 0; j < 2; j++) {
        int idx = tid + j * 256;
        int n = idx >> 2, c = idx & 3;
        bsrc[j] = wde + (size_t)(n0 + n) * FDIM + c * 8;
        bdst[j] = (uint32_t)(n * 80 + c * 16);
    }

    uint32_t aoff[4];
#pragma unroll
    for (int m = 0; m < 4; m++)
        aoff[m] = (uint32_t)(((wm * 64 + m * 16 + (lane & 15)) * 40 + (lane >> 4) * 8) * 2);
    uint32_t boff[2];
#pragma unroll
    for (int p = 0; p < 2; p++)
        boff[p] = (uint32_t)(((wn * 32 + p * 16 + (lane & 7) + ((lane >> 4) & 1) * 8) * 40 +
                              ((lane >> 3) & 1) * 8) * 2);

    float acc[4][4][4];
#pragma unroll
    for (int m = 0; m < 4; m++)
#pragma unroll
        for (int n = 0; n < 4; n++)
#pragma unroll
            for (int q = 0; q < 4; q++) acc[m][n][q] = 0.f;

    const int KI = FDIM / 32;  // 128

#define DN_ISSUE(s, k0)                                                  \
    do {                                                                 \
        uint32_t ab = su + (uint32_t)(s) * STG;                          \
        _Pragma("unroll") for (int j = 0; j < 2; j++)                    \
            CP16(ab + adst[j], asrc[j] + (k0), asz[j]);                  \
        _Pragma("unroll") for (int j = 0; j < 2; j++)                    \
            CP16(ab + 10240u + bdst[j], bsrc[j] + (k0), 16u);            \
        CP_COMMIT();                                                     \
    } while (0)

    DN_ISSUE(0, 0);
    DN_ISSUE(1, 32);
    DN_ISSUE(2, 64);
    DN_ISSUE(3, 96);

    int sC = 0, sP = 4;
    for (int i = 0; i < KI; i++) {
        if (i <= KI - 4) CP_WAITG3();
        else if (i == KI - 3) CP_WAITG2();
        else if (i == KI - 2) CP_WAITG1();
        else CP_WAIT0();
        __syncthreads();
        if (i + 4 < KI) {
            DN_ISSUE(sP, (i + 4) * 32);
            sP = (sP == 4) ? 0 : sP + 1;
        }
        uint32_t ab = su + (uint32_t)sC * STG;
        sC = (sC == 4) ? 0 : sC + 1;
#pragma unroll
        for (int kk = 0; kk < 2; kk++) {
            uint32_t kb = (uint32_t)(kk * 32);
            uint32_t af[4][4], bf[2][4];
#pragma unroll
            for (int m = 0; m < 4; m++)
                LDSM4(af[m][0], af[m][1], af[m][2], af[m][3], ab + aoff[m] + kb);
#pragma unroll
            for (int p = 0; p < 2; p++)
                LDSM4(bf[p][0], bf[p][1], bf[p][2], bf[p][3], ab + 10240u + boff[p] + kb);
#pragma unroll
            for (int m = 0; m < 4; m++)
#pragma unroll
                for (int n = 0; n < 4; n++)
                    mma16(acc[m][n], af[m], bf[n >> 1] + (n & 1) * 2);
        }
    }
#undef DN_ISSUE

    // epilogue: weighted scatter
#pragma unroll
    for (int m = 0; m < 4; m++) {
#pragma unroll
        for (int half = 0; half < 2; half++) {
            int R = wm * 64 + m * 16 + gid + half * 8;
            int r = base + R;
            if (r >= cnt) continue;
            int t = g_tok[e * TOKS + r];
            int sl = g_slot[e * TOKS + r];
            float w = g_wt[e * TOKS + r];
            size_t yb = ((size_t)sl * TOKS + t) * HDIM + n0;
#pragma unroll
            for (int n = 0; n < 4; n++) {
                int col = wn * 32 + n * 8 + 2 * tig;
                float v0 = acc[m][n][half * 2 + 0], v1 = acc[m][n][half * 2 + 1];
                *reinterpret_cast<float2*>(g_y + yb + col) = make_float2(w * v0, w * v1);
            }
        }
    }
}

// ---------------- combine: out = y[slot0] + y[slot1] ----------------
__global__ void moe_combine(float* __restrict__ out) {
    size_t i = (size_t)blockIdx.x * 256 + threadIdx.x;
    const float4* y0 = reinterpret_cast<const float4*>(g_y);
    const float4* y1 = y0 + (size_t)TOKS * HDIM / 4;
    float4 a = y0[i], b = y1[i];
    reinterpret_cast<float4*>(out)[i] = make_float4(a.x + b.x, a.y + b.y, a.z + b.z, a.w + b.w);
}

// ---------------- launch ----------------
// Launch order puts moe_gateup at stream index 5 so ncu (-s 5 -c 1) captures it.
extern "C" void kernel_launch(void* const* d_in, const int* in_sizes, int n_in,
                              void* d_out, int out_size) {
    const float* x   = (const float*)d_in[0];
    const float* wg  = (const float*)d_in[1];
    const float* wgp = (const float*)d_in[2];
    const float* wup = (const float*)d_in[3];
    const float* wdp = (const float*)d_in[4];
    float* out = (float*)d_out;

    cudaFuncSetAttribute(moe_gateup, cudaFuncAttributeMaxDynamicSharedMemorySize, 102400);
    cudaFuncSetAttribute(moe_down,   cudaFuncAttributeMaxDynamicSharedMemorySize, 102400);

    conv_x<<<(TOKS * HDIM / 8) / 256, 256>>>(x);                 // #0 (also zeroes g_cnt)
    {
        __half* dwg; cudaGetSymbolAddress((void**)&dwg, g_wg16);
        __half* dwu; cudaGetSymbolAddress((void**)&dwu, g_wu16);
        __half* dwd; cudaGetSymbolAddress((void**)&dwd, g_wd16);
        conv_w<<<dim3(FDIM / 64, HDIM / 64, NEXP), 256>>>(wgp, dwg, HDIM, FDIM);  // #1
        conv_w<<<dim3(FDIM / 64, HDIM / 64, NEXP), 256>>>(wup, dwu, HDIM, FDIM);  // #2
        conv_w<<<dim3(HDIM / 64, FDIM / 64, NEXP), 256>>>(wdp, dwd, FDIM, HDIM);  // #3
    }
    moe_router<<<TOKS / 8, 256>>>(x, wg, out + (size_t)TOKS * HDIM);              // #4
    moe_gateup<<<dim3(FDIM / 64, 32, NEXP), 256, 102400>>>();                     // #5
    moe_down<<<dim3(HDIM / 128, 32, NEXP), 256, 102400>>>();                      // #6
    moe_combine<<<(TOKS * HDIM / 4) / 256, 256>>>(out);                           // #7
}

// round 10
// speedup vs baseline: 2.4826x; 1.1006x over previous
#include <cuda_runtime.h>
#include <cuda_fp16.h>
#include <cstdint>

#define TOKS 8192
#define HDIM 1024
#define FDIM 4096
#define NEXP 8

// ---------------- scratch (__device__ globals; no allocation) ----------------
__device__ int    g_cnt[NEXP];
__device__ int    g_tok[NEXP * TOKS];
__device__ int    g_slot[NEXP * TOKS];
__device__ float  g_wt[NEXP * TOKS];
__device__ __half g_x16[(size_t)TOKS * HDIM];            // fp16 x (16 MB)
__device__ __half g_wg16[(size_t)NEXP * FDIM * HDIM];    // gate W, [e][n][k] (64 MB)
__device__ __half g_wu16[(size_t)NEXP * FDIM * HDIM];    // up   W, [e][n][k] (64 MB)
__device__ __half g_wd16[(size_t)NEXP * HDIM * FDIM];    // down W, [e][n][k] (64 MB)
__device__ __half g_h16[(size_t)2 * TOKS * FDIM];        // hidden (128 MB)
__device__ float  g_y[(size_t)2 * TOKS * HDIM];          // slot outputs (64 MB)

// ---------------- helpers ----------------
static __device__ __forceinline__ uint32_t smem_u32(const void* p) {
    uint32_t a;
    asm("{ .reg .u64 t; cvta.to.shared.u64 t, %1; cvt.u32.u64 %0, t; }" : "=r"(a) : "l"(p));
    return a;
}
static __device__ __forceinline__ void mma16(float* c, const uint32_t* a, const uint32_t* b) {
    asm volatile(
        "mma.sync.aligned.m16n8k16.row.col.f32.f16.f16.f32 "
        "{%0,%1,%2,%3}, {%4,%5,%6,%7}, {%8,%9}, {%0,%1,%2,%3};"
        : "+f"(c[0]), "+f"(c[1]), "+f"(c[2]), "+f"(c[3])
        : "r"(a[0]), "r"(a[1]), "r"(a[2]), "r"(a[3]), "r"(b[0]), "r"(b[1]));
}
#define LDSM4(r0, r1, r2, r3, addr)                                              \
    asm volatile("ldmatrix.sync.aligned.m8n8.x4.shared.b16 {%0,%1,%2,%3}, [%4];" \
                 : "=r"(r0), "=r"(r1), "=r"(r2), "=r"(r3) : "r"(addr))
#define CP16(dst, src, sz) \
    asm volatile("cp.async.cg.shared.global [%0], [%1], 16, %2;\n" ::"r"(dst), "l"(src), "r"(sz))
#define CP_COMMIT() asm volatile("cp.async.commit_group;\n" ::: "memory")
#define CP_WAITG1() asm volatile("cp.async.wait_group 1;\n" ::: "memory")
#define CP_WAIT0()  asm volatile("cp.async.wait_group 0;\n" ::: "memory")

static __device__ __forceinline__ float silu(float v) { return v / (1.f + __expf(-v)); }

static __device__ __forceinline__ int expert_off(int e) {
    int off = 0;
#pragma unroll
    for (int i = 0; i < NEXP; i++) if (i < e) off += g_cnt[i];
    return off;
}

// ---------------- convert x -> fp16 (also zeroes g_cnt) ----------------
__global__ void conv_x(const float* __restrict__ x) {
    if (blockIdx.x == 0 && threadIdx.x < NEXP) g_cnt[threadIdx.x] = 0;
    size_t i = ((size_t)blockIdx.x * 256 + threadIdx.x) * 8;
    float4 a = *reinterpret_cast<const float4*>(x + i);
    float4 b = *reinterpret_cast<const float4*>(x + i + 4);
    __half2 h[4];
    h[0] = __floats2half2_rn(a.x, a.y);
    h[1] = __floats2half2_rn(a.z, a.w);
    h[2] = __floats2half2_rn(b.x, b.y);
    h[3] = __floats2half2_rn(b.z, b.w);
    *reinterpret_cast<uint4*>(g_x16 + i) = *reinterpret_cast<uint4*>(h);
}

// ---------------- convert+transpose W: [e][k][n] fp32 -> [e][n][k] fp16 ----------------
__global__ void conv_w(const float* __restrict__ src, __half* __restrict__ dst,
                       int Kd, int Nd) {
    __shared__ float t[64][65];
    int e = blockIdx.z;
    int k0 = blockIdx.y * 64, n0 = blockIdx.x * 64;
    const float* S = src + ((size_t)e * Kd + k0) * Nd + n0;
    int tid = threadIdx.x;
    int kr = tid >> 4, nc = (tid & 15) * 4;
#pragma unroll
    for (int j = 0; j < 4; j++) {
        float4 v = *reinterpret_cast<const float4*>(S + (size_t)(kr + j * 16) * Nd + nc);
        t[kr + j * 16][nc + 0] = v.x;
        t[kr + j * 16][nc + 1] = v.y;
        t[kr + j * 16][nc + 2] = v.z;
        t[kr + j * 16][nc + 3] = v.w;
    }
    __syncthreads();
    int nr = tid >> 2, kc = (tid & 3) * 16;
    __half hb[16];
#pragma unroll
    for (int q = 0; q < 16; q++) hb[q] = __float2half_rn(t[kc + q][nr]);
    __half* D = dst + ((size_t)e * Nd + n0 + nr) * Kd + k0 + kc;
    *reinterpret_cast<uint4*>(D)     = *reinterpret_cast<uint4*>(hb);
    *reinterpret_cast<uint4*>(D + 8) = *reinterpret_cast<uint4*>(hb + 8);
}

// ---------------- router ----------------
__global__ void moe_router(const float* __restrict__ x, const float* __restrict__ wg,
                           float* __restrict__ logits_out) {
    int t = blockIdx.x * 8 + (threadIdx.x >> 5);
    int lane = threadIdx.x & 31;
    const float* xr = x + (size_t)t * HDIM;
    float acc[8] = {0.f, 0.f, 0.f, 0.f, 0.f, 0.f, 0.f, 0.f};
    for (int j = lane; j < HDIM; j += 32) {
        float xv = xr[j];
        const float4* w4 = reinterpret_cast<const float4*>(wg + (size_t)j * NEXP);
        float4 a = w4[0], b = w4[1];
        acc[0] += xv * a.x; acc[1] += xv * a.y; acc[2] += xv * a.z; acc[3] += xv * a.w;
        acc[4] += xv * b.x; acc[5] += xv * b.y; acc[6] += xv * b.z; acc[7] += xv * b.w;
    }
#pragma unroll
    for (int o = 16; o > 0; o >>= 1)
#pragma unroll
        for (int k = 0; k < 8; k++) acc[k] += __shfl_xor_sync(0xffffffffu, acc[k], o);

    if (lane == 0) {
#pragma unroll
        for (int k = 0; k < 8; k++) logits_out[(size_t)t * NEXP + k] = acc[k];
        int i0 = 0; float v0 = acc[0];
#pragma unroll
        for (int k = 1; k < 8; k++) if (acc[k] > v0) { v0 = acc[k]; i0 = k; }
        int i1 = -1; float v1 = -3.4e38f;
#pragma unroll
        for (int k = 0; k < 8; k++) if (k != i0 && acc[k] > v1) { v1 = acc[k]; i1 = k; }
        float w0 = 1.f / (1.f + __expf(v1 - v0));
        float w1 = 1.f - w0;
        int p0 = atomicAdd(&g_cnt[i0], 1);
        g_tok[i0 * TOKS + p0] = t; g_slot[i0 * TOKS + p0] = 0; g_wt[i0 * TOKS + p0] = w0;
        int p1 = atomicAdd(&g_cnt[i1], 1);
        g_tok[i1 * TOKS + p1] = t; g_slot[i1 * TOKS + p1] = 1; g_wt[i1 * TOKS + p1] = w1;
    }
}

// ---------------- fused gate+up GEMM (fp16, ldmatrix, BK=64, 3-stage) ----------------
// BM=128, BN=64 per side, BK=64, pitch 72 halves (144 B) — conflict-free & 16B-aligned.
// Stage: A 128*144=18432B, Bg 64*144=9216B, Bu 9216B -> 36864B. 3 stages = 110592B.
__global__ void __launch_bounds__(256, 2)
moe_gateup() {
    int e = blockIdx.z;
    int cnt = g_cnt[e];
    int base = blockIdx.y * 128;
    if (base >= cnt) return;
    int n0 = blockIdx.x * 64;
    int off = expert_off(e);
    const __half* wge = g_wg16 + (size_t)e * FDIM * HDIM;
    const __half* wue = g_wu16 + (size_t)e * FDIM * HDIM;

    extern __shared__ char smem8[];
    uint32_t su = smem_u32(smem8);
    const uint32_t STG = 36864;

    int tid = threadIdx.x, lane = tid & 31;
    int gid = lane >> 2, tig = lane & 3;
    int wid = tid >> 5, wm = wid >> 2, wn = wid & 3;

    // cp.async descriptors: A 128 rows x 8 chunks -> 4/thread
    const __half* asrc[4]; uint32_t asz[4], adst[4];
#pragma unroll
    for (int j = 0; j < 4; j++) {
        int idx = tid + j * 256;
        int row = idx >> 3, c = idx & 7;
        int r = base + row;
        bool v = r < cnt;
        int tok = v ? g_tok[e * TOKS + r] : 0;
        asrc[j] = g_x16 + (size_t)tok * HDIM + c * 8;
        asz[j] = v ? 16u : 0u;
        adst[j] = (uint32_t)(row * 144 + c * 16);
    }
    // B per side: 64 rows x 8 chunks -> 2/thread
    const __half* gsrc[2]; const __half* usrc[2]; uint32_t bdst[2];
#pragma unroll
    for (int j = 0; j < 2; j++) {
        int idx = tid + j * 256;
        int n = idx >> 3, c = idx & 7;
        gsrc[j] = wge + (size_t)(n0 + n) * HDIM + c * 8;
        usrc[j] = wue + (size_t)(n0 + n) * HDIM + c * 8;
        bdst[j] = (uint32_t)(n * 144 + c * 16);
    }

    // ldmatrix per-lane byte offsets (within a stage), pitch 72 halves
    uint32_t aoff[4];
#pragma unroll
    for (int m = 0; m < 4; m++)
        aoff[m] = (uint32_t)(((wm * 64 + m * 16 + (lane & 15)) * 72 + (lane >> 4) * 8) * 2);
    uint32_t boff = (uint32_t)(((wn * 16 + (lane & 7) + ((lane >> 4) & 1) * 8) * 72 +
                                ((lane >> 3) & 1) * 8) * 2);

    float accG[4][2][4], accU[4][2][4];
#pragma unroll
    for (int m = 0; m < 4; m++)
#pragma unroll
        for (int n = 0; n < 2; n++)
#pragma unroll
            for (int q = 0; q < 4; q++) { accG[m][n][q] = 0.f; accU[m][n][q] = 0.f; }

    const int KI = HDIM / 64;  // 16

#define GU_ISSUE(s, k0)                                                  \
    do {                                                                 \
        uint32_t ab = su + (uint32_t)(s) * STG;                          \
        _Pragma("unroll") for (int j = 0; j < 4; j++)                    \
            CP16(ab + adst[j], asrc[j] + (k0), asz[j]);                  \
        _Pragma("unroll") for (int j = 0; j < 2; j++)                    \
            CP16(ab + 18432u + bdst[j], gsrc[j] + (k0), 16u);            \
        _Pragma("unroll") for (int j = 0; j < 2; j++)                    \
            CP16(ab + 27648u + bdst[j], usrc[j] + (k0), 16u);            \
        CP_COMMIT();                                                     \
    } while (0)

    GU_ISSUE(0, 0);
    GU_ISSUE(1, 64);

    int sC = 0, sP = 2;
    for (int i = 0; i < KI; i++) {
        if (i + 1 < KI) CP_WAITG1(); else CP_WAIT0();
        __syncthreads();
        if (i + 2 < KI) {
            GU_ISSUE(sP, (i + 2) * 64);
            sP = (sP == 2) ? 0 : sP + 1;
        }
        uint32_t ab = su + (uint32_t)sC * STG;
        sC = (sC == 2) ? 0 : sC + 1;
#pragma unroll
        for (int kk = 0; kk < 4; kk++) {
            uint32_t kb = (uint32_t)(kk * 32);  // 16 halves per k-step
            uint32_t af[4][4], bg[4], bu[4];
#pragma unroll
            for (int m = 0; m < 4; m++)
                LDSM4(af[m][0], af[m][1], af[m][2], af[m][3], ab + aoff[m] + kb);
            LDSM4(bg[0], bg[1], bg[2], bg[3], ab + 18432u + boff + kb);
            LDSM4(bu[0], bu[1], bu[2], bu[3], ab + 27648u + boff + kb);
#pragma unroll
            for (int m = 0; m < 4; m++)
#pragma unroll
                for (int n = 0; n < 2; n++) {
                    mma16(accG[m][n], af[m], bg + n * 2);
                    mma16(accU[m][n], af[m], bu + n * 2);
                }
        }
    }
#undef GU_ISSUE

    // epilogue: g_h16 = fp16(silu(g) * u)
#pragma unroll
    for (int m = 0; m < 4; m++) {
#pragma unroll
        for (int half = 0; half < 2; half++) {
            int R = wm * 64 + m * 16 + gid + half * 8;
            int r = base + R;
            if (r >= cnt) continue;
            size_t rb = (size_t)(off + r) * FDIM + n0;
#pragma unroll
            for (int n = 0; n < 2; n++) {
                int col = wn * 16 + n * 8 + 2 * tig;
                float h0 = silu(accG[m][n][half * 2 + 0]) * accU[m][n][half * 2 + 0];
                float h1 = silu(accG[m][n][half * 2 + 1]) * accU[m][n][half * 2 + 1];
                *reinterpret_cast<__half2*>(g_h16 + rb + col) = __floats2half2_rn(h0, h1);
            }
        }
    }
}

// ---------------- down GEMM: y[slot][tok] = w * (g_h16 @ Wd), BK=64, 3-stage ----------------
// Stage: A 18432B + B 128*144=18432B = 36864B. 3 stages = 110592B.
__global__ void __launch_bounds__(256, 2)
moe_down() {
    int e = blockIdx.z;
    int cnt = g_cnt[e];
    int base = blockIdx.y * 128;
    if (base >= cnt) return;
    int n0 = blockIdx.x * 128;
    int off = expert_off(e);
    const __half* wde = g_wd16 + (size_t)e * HDIM * FDIM;

    extern __shared__ char smem8[];
    uint32_t su = smem_u32(smem8);
    const uint32_t STG = 36864;

    int tid = threadIdx.x, lane = tid & 31;
    int gid = lane >> 2, tig = lane & 3;
    int wid = tid >> 5, wm = wid >> 2, wn = wid & 3;

    const __half* asrc[4]; uint32_t asz[4], adst[4];
#pragma unroll
    for (int j = 0; j < 4; j++) {
        int idx = tid + j * 256;
        int row = idx >> 3, c = idx & 7;
        int r = base + row;
        bool v = r < cnt;
        size_t arow = v ? (size_t)(off + r) : 0;
        asrc[j] = g_h16 + arow * FDIM + c * 8;
        asz[j] = v ? 16u : 0u;
        adst[j] = (uint32_t)(row * 144 + c * 16);
    }
    const __half* bsrc[4]; uint32_t bdst[4];
#pragma unroll
    for (int j = 0; j < 4; j++) {
        int idx = tid + j * 256;
        int n = idx >> 3, c = idx & 7;
        bsrc[j] = wde + (size_t)(n0 + n) * FDIM + c * 8;
        bdst[j] = (uint32_t)(n * 144 + c * 16);
    }

    uint32_t aoff[4];
#pragma unroll
    for (int m = 0; m < 4; m++)
        aoff[m] = (uint32_t)(((wm * 64 + m * 16 + (lane & 15)) * 72 + (lane >> 4) * 8) * 2);
    uint32_t boff[2];
#pragma unroll
    for (int p = 0; p < 2; p++)
        boff[p] = (uint32_t)(((wn * 32 + p * 16 + (lane & 7) + ((lane >> 4) & 1) * 8) * 72 +
                              ((lane >> 3) & 1) * 8) * 2);

    float acc[4][4][4];
#pragma unroll
    for (int m = 0; m < 4; m++)
#pragma unroll
        for (int n = 0; n < 4; n++)
#pragma unroll
            for (int q = 0; q < 4; q++) acc[m][n][q] = 0.f;

    const int KI = FDIM / 64;  // 64

#define DN_ISSUE(s, k0)                                                  \
    do {                                                                 \
        uint32_t ab = su + (uint32_t)(s) * STG;                          \
        _Pragma("unroll") for (int j = 0; j < 4; j++)                    \
            CP16(ab + adst[j], asrc[j] + (k0), asz[j]);                  \
        _Pragma("unroll") for (int j = 0; j < 4; j++)                    \
            CP16(ab + 18432u + bdst[j], bsrc[j] + (k0), 16u);            \
        CP_COMMIT();                                                     \
    } while (0)

    DN_ISSUE(0, 0);
    DN_ISSUE(1, 64);

    int sC = 0, sP = 2;
    for (int i = 0; i < KI; i++) {
        if (i + 1 < KI) CP_WAITG1(); else CP_WAIT0();
        __syncthreads();
        if (i + 2 < KI) {
            DN_ISSUE(sP, (i + 2) * 64);
            sP = (sP == 2) ? 0 : sP + 1;
        }
        uint32_t ab = su + (uint32_t)sC * STG;
        sC = (sC == 2) ? 0 : sC + 1;
#pragma unroll
        for (int kk = 0; kk < 4; kk++) {
            uint32_t kb = (uint32_t)(kk * 32);
            uint32_t af[4][4], bf[2][4];
#pragma unroll
            for (int m = 0; m < 4; m++)
                LDSM4(af[m][0], af[m][1], af[m][2], af[m][3], ab + aoff[m] + kb);
#pragma unroll
            for (int p = 0; p < 2; p++)
                LDSM4(bf[p][0], bf[p][1], bf[p][2], bf[p][3], ab + 18432u + boff[p] + kb);
#pragma unroll
            for (int m = 0; m < 4; m++)
#pragma unroll
                for (int n = 0; n < 4; n++)
                    mma16(acc[m][n], af[m], bf[n >> 1] + (n & 1) * 2);
        }
    }
#undef DN_ISSUE

    // epilogue: weighted scatter
#pragma unroll
    for (int m = 0; m < 4; m++) {
#pragma unroll
        for (int half = 0; half < 2; half++) {
            int R = wm * 64 + m * 16 + gid + half * 8;
            int r = base + R;
            if (r >= cnt) continue;
            int t = g_tok[e * TOKS + r];
            int sl = g_slot[e * TOKS + r];
            float w = g_wt[e * TOKS + r];
            size_t yb = ((size_t)sl * TOKS + t) * HDIM + n0;
#pragma unroll
            for (int n = 0; n < 4; n++) {
                int col = wn * 32 + n * 8 + 2 * tig;
                float v0 = acc[m][n][half * 2 + 0], v1 = acc[m][n][half * 2 + 1];
                *reinterpret_cast<float2*>(g_y + yb + col) = make_float2(w * v0, w * v1);
            }
        }
    }
}

// ---------------- combine: out = y[slot0] + y[slot1] ----------------
__global__ void moe_combine(float* __restrict__ out) {
    size_t i = (size_t)blockIdx.x * 256 + threadIdx.x;
    const float4* y0 = reinterpret_cast<const float4*>(g_y);
    const float4* y1 = y0 + (size_t)TOKS * HDIM / 4;
    float4 a = y0[i], b = y1[i];
    reinterpret_cast<float4*>(out)[i] = make_float4(a.x + b.x, a.y + b.y, a.z + b.z, a.w + b.w);
}

// ---------------- launch ----------------
extern "C" void kernel_launch(void* const* d_in, const int* in_sizes, int n_in,
                              void* d_out, int out_size) {
    const float* x   = (const float*)d_in[0];
    const float* wg  = (const float*)d_in[1];
    const float* wgp = (const float*)d_in[2];
    const float* wup = (const float*)d_in[3];
    const float* wdp = (const float*)d_in[4];
    float* out = (float*)d_out;

    cudaFuncSetAttribute(moe_gateup, cudaFuncAttributeMaxDynamicSharedMemorySize, 110592);
    cudaFuncSetAttribute(moe_down,   cudaFuncAttributeMaxDynamicSharedMemorySize, 110592);

    conv_x<<<(TOKS * HDIM / 8) / 256, 256>>>(x);                 // #0 (also zeroes g_cnt)
    {
        __half* dwg; cudaGetSymbolAddress((void**)&dwg, g_wg16);
        __half* dwu; cudaGetSymbolAddress((void**)&dwu, g_wu16);
        __half* dwd; cudaGetSymbolAddress((void**)&dwd, g_wd16);
        conv_w<<<dim3(FDIM / 64, HDIM / 64, NEXP), 256>>>(wgp, dwg, HDIM, FDIM);  // #1
        conv_w<<<dim3(FDIM / 64, HDIM / 64, NEXP), 256>>>(wup, dwu, HDIM, FDIM);  // #2
        conv_w<<<dim3(HDIM / 64, FDIM / 64, NEXP), 256>>>(wdp, dwd, FDIM, HDIM);  // #3
    }
    moe_router<<<TOKS / 8, 256>>>(x, wg, out + (size_t)TOKS * HDIM);              // #4
    moe_gateup<<<dim3(FDIM / 64, 32, NEXP), 256, 110592>>>();                     // #5
    moe_down<<<dim3(HDIM / 128, 32, NEXP), 256, 110592>>>();                      // #6
    moe_combine<<<(TOKS * HDIM / 4) / 256, 256>>>(out);                           // #7
}